// round 2
// baseline (speedup 1.0000x reference)
#include <cuda_runtime.h>
#include <cuda_bf16.h>
#include <math.h>

// Problem constants (fixed shapes for this dataset)
#define Bb   8
#define Cc   256
#define Hh   64
#define Ww   64
#define HW   (Hh*Ww)          // 4096
#define Nn   (Bb*HW)          // 32768
#define KD   1024
#define OUT_ELEMS ((size_t)Bb*Cc*HW)   // 8388608

#define EPS_NORM 1e-12f
#define EPS_Z    1e-6f
#define RATE     0.999f

// ---------------- scratch (device globals; no allocation allowed) -----------
__device__ float d_xf  [(size_t)Nn*Cc];
__device__ float d_xn  [(size_t)Nn*Cc];
__device__ float d_g   [(size_t)Nn*Cc];
__device__ float d_xo  [(size_t)Nn*Cc];
__device__ float d_ot  [(size_t)Nn*Cc];
__device__ float d_qcat[(size_t)Nn*2*Cc];
__device__ float d_mn0 [(size_t)KD*Cc];
__device__ float d_mnew[(size_t)KD*Cc];
__device__ float d_kk  [(size_t)KD*2*Cc];
__device__ float d_sums[(size_t)KD*Cc];
__device__ float d_counts[KD];
__device__ int   d_ind [Nn];
__device__ float d_p   [Cc];
__device__ float d_kmean[2*Cc];
__device__ float d_kvfull[(size_t)2*Cc*Cc]; // 512 x 256
__device__ float d_Bmat  [(size_t)2*Cc*Cc]; // 512 x 256
__device__ float d_z [Nn];
__device__ float d_z2[Nn];

// ---------------- small kernels ---------------------------------------------
__global__ void k_prep_p(const float* __restrict__ power) {
    int c = threadIdx.x;
    float pw = power[c];
    d_p[c] = 1.0f + 4.0f / (1.0f + __expf(-pw));
}

__global__ void k_zero() {
    int idx = blockIdx.x * blockDim.x + threadIdx.x;
    int tot = KD*Cc + KD;
    if (idx < KD*Cc) d_sums[idx] = 0.f;
    else if (idx < tot) d_counts[idx - KD*Cc] = 0.f;
}

// normalize units_w rows -> d_mn0 (one warp per row, 8 rows/block)
__global__ void k_norm_units(const float* __restrict__ uw) {
    int row  = blockIdx.x * 8 + (threadIdx.x >> 5);
    int lane = threadIdx.x & 31;
    const float* r = uw + (size_t)row * Cc;
    float ss = 0.f;
    for (int j = lane; j < Cc; j += 32) { float v = r[j]; ss += v*v; }
    #pragma unroll
    for (int o = 16; o; o >>= 1) ss += __shfl_xor_sync(0xffffffffu, ss, o);
    float inv = 1.0f / fmaxf(sqrtf(ss), EPS_NORM);
    for (int j = lane; j < Cc; j += 32) d_mn0[(size_t)row*Cc + j] = r[j]*inv;
}

// x (B,C,HW) -> xf (B*HW, C)  tiled transpose
__global__ void k_transpose_x(const float* __restrict__ x) {
    __shared__ float tile[32][33];
    int b  = blockIdx.z;
    int c0 = blockIdx.y * 32, s0 = blockIdx.x * 32;
    int tx = threadIdx.x, ty = threadIdx.y;
    #pragma unroll
    for (int r = ty; r < 32; r += 8)
        tile[r][tx] = x[((size_t)(b*Cc + c0 + r))*HW + s0 + tx];
    __syncthreads();
    #pragma unroll
    for (int r = ty; r < 32; r += 8)
        d_xf[((size_t)b*HW + s0 + r)*Cc + c0 + tx] = tile[tx][r];
}

// row L2-normalize xf -> xn (one warp per row)
__global__ void k_rownorm() {
    int row  = blockIdx.x * 8 + (threadIdx.x >> 5);
    int lane = threadIdx.x & 31;
    const float* r = d_xf + (size_t)row * Cc;
    float ss = 0.f;
    for (int j = lane; j < Cc; j += 32) { float v = r[j]; ss += v*v; }
    #pragma unroll
    for (int o = 16; o; o >>= 1) ss += __shfl_xor_sync(0xffffffffu, ss, o);
    float inv = 1.0f / fmaxf(sqrtf(ss), EPS_NORM);
    for (int j = lane; j < Cc; j += 32) d_xn[(size_t)row*Cc + j] = r[j]*inv;
}

// ---------------- GEMMs (64x64x16 tile, 4x4 microtile, 256 thr) -------------
// g = xf (N x 256) @ g_w^T (256 x 256) + g_b     [A,C are device globals]
__global__ __launch_bounds__(256)
void k_gemm_g(const float* __restrict__ Bm, const float* __restrict__ bias)
{
    __shared__ float As[16][68];
    __shared__ float Bs[16][68];
    int tid = threadIdx.x;
    int tx = tid & 15, ty = tid >> 4;
    int rowBase = blockIdx.y * 64, colBase = blockIdx.x * 64;
    float acc[4][4] = {};
    for (int k0 = 0; k0 < Cc; k0 += 16) {
        #pragma unroll
        for (int e = 0; e < 4; e++) {
            int t = tid + e*256;
            int r = t >> 4, kk = t & 15;
            As[kk][r] = d_xf[(size_t)(rowBase + r)*Cc + k0 + kk];
        }
        #pragma unroll
        for (int e = 0; e < 4; e++) {
            int t = tid + e*256;
            int c = t >> 4, kk = t & 15;
            Bs[kk][c] = Bm[(size_t)(colBase + c)*Cc + k0 + kk];
        }
        __syncthreads();
        #pragma unroll
        for (int kk = 0; kk < 16; kk++) {
            float a[4], bv[4];
            #pragma unroll
            for (int i = 0; i < 4; i++) a[i]  = As[kk][ty*4 + i];
            #pragma unroll
            for (int j = 0; j < 4; j++) bv[j] = Bs[kk][tx*4 + j];
            #pragma unroll
            for (int i = 0; i < 4; i++)
                #pragma unroll
                for (int j = 0; j < 4; j++) acc[i][j] += a[i]*bv[j];
        }
        __syncthreads();
    }
    #pragma unroll
    for (int i = 0; i < 4; i++) {
        int r = rowBase + ty*4 + i;
        #pragma unroll
        for (int j = 0; j < 4; j++) {
            int c = colBase + tx*4 + j;
            d_g[(size_t)r*Cc + c] = acc[i][j] + bias[c];
        }
    }
}

// score = xn (N x 256) @ mn0^T (256 x 1024)      [A,B are device globals]
__global__ __launch_bounds__(256)
void k_gemm_score(float* __restrict__ score)
{
    __shared__ float As[16][68];
    __shared__ float Bs[16][68];
    int tid = threadIdx.x;
    int tx = tid & 15, ty = tid >> 4;
    int rowBase = blockIdx.y * 64, colBase = blockIdx.x * 64;
    float acc[4][4] = {};
    for (int k0 = 0; k0 < Cc; k0 += 16) {
        #pragma unroll
        for (int e = 0; e < 4; e++) {
            int t = tid + e*256;
            int r = t >> 4, kk = t & 15;
            As[kk][r] = d_xn[(size_t)(rowBase + r)*Cc + k0 + kk];
        }
        #pragma unroll
        for (int e = 0; e < 4; e++) {
            int t = tid + e*256;
            int c = t >> 4, kk = t & 15;
            Bs[kk][c] = d_mn0[(size_t)(colBase + c)*Cc + k0 + kk];
        }
        __syncthreads();
        #pragma unroll
        for (int kk = 0; kk < 16; kk++) {
            float a[4], bv[4];
            #pragma unroll
            for (int i = 0; i < 4; i++) a[i]  = As[kk][ty*4 + i];
            #pragma unroll
            for (int j = 0; j < 4; j++) bv[j] = Bs[kk][tx*4 + j];
            #pragma unroll
            for (int i = 0; i < 4; i++)
                #pragma unroll
                for (int j = 0; j < 4; j++) acc[i][j] += a[i]*bv[j];
        }
        __syncthreads();
    }
    #pragma unroll
    for (int i = 0; i < 4; i++) {
        int r = rowBase + ty*4 + i;
        #pragma unroll
        for (int j = 0; j < 4; j++)
            score[(size_t)r*KD + colBase + tx*4 + j] = acc[i][j];
    }
}

// KVfull[512,256] = kk^T (512x1024) @ mnew (1024x256)
__global__ __launch_bounds__(256)
void k_gemm_kv()
{
    __shared__ float As[16][68];
    __shared__ float Bs[16][68];
    int tid = threadIdx.x;
    int tx = tid & 15, ty = tid >> 4;
    int rowBase = blockIdx.y * 64, colBase = blockIdx.x * 64;
    float acc[4][4] = {};
    for (int k0 = 0; k0 < KD; k0 += 16) {
        #pragma unroll
        for (int e = 0; e < 4; e++) {
            int t = tid + e*256;
            int kk = t >> 6, r = t & 63;
            As[kk][r] = d_kk[(size_t)(k0 + kk)*(2*Cc) + rowBase + r];
        }
        #pragma unroll
        for (int e = 0; e < 4; e++) {
            int t = tid + e*256;
            int kk = t >> 6, c = t & 63;
            Bs[kk][c] = d_mnew[(size_t)(k0 + kk)*Cc + colBase + c];
        }
        __syncthreads();
        #pragma unroll
        for (int kk = 0; kk < 16; kk++) {
            float a[4], bv[4];
            #pragma unroll
            for (int i = 0; i < 4; i++) a[i]  = As[kk][ty*4 + i];
            #pragma unroll
            for (int j = 0; j < 4; j++) bv[j] = Bs[kk][tx*4 + j];
            #pragma unroll
            for (int i = 0; i < 4; i++)
                #pragma unroll
                for (int j = 0; j < 4; j++) acc[i][j] += a[i]*bv[j];
        }
        __syncthreads();
    }
    #pragma unroll
    for (int i = 0; i < 4; i++) {
        int r = rowBase + ty*4 + i;
        #pragma unroll
        for (int j = 0; j < 4; j++)
            d_kvfull[(size_t)r*Cc + colBase + tx*4 + j] = acc[i][j];
    }
}

// xo = qcat (N x 512) @ Bmat (512 x 256), epilogue: * z (col<128) else z2
__global__ __launch_bounds__(256)
void k_gemm_xo()
{
    __shared__ float As[16][68];
    __shared__ float Bs[16][68];
    int tid = threadIdx.x;
    int tx = tid & 15, ty = tid >> 4;
    int rowBase = blockIdx.y * 64, colBase = blockIdx.x * 64;
    float acc[4][4] = {};
    for (int k0 = 0; k0 < 2*Cc; k0 += 16) {
        #pragma unroll
        for (int e = 0; e < 4; e++) {
            int t = tid + e*256;
            int r = t >> 4, kk = t & 15;
            As[kk][r] = d_qcat[(size_t)(rowBase + r)*(2*Cc) + k0 + kk];
        }
        #pragma unroll
        for (int e = 0; e < 4; e++) {
            int t = tid + e*256;
            int kk = t >> 6, c = t & 63;
            Bs[kk][c] = d_Bmat[(size_t)(k0 + kk)*Cc + colBase + c];
        }
        __syncthreads();
        #pragma unroll
        for (int kk = 0; kk < 16; kk++) {
            float a[4], bv[4];
            #pragma unroll
            for (int i = 0; i < 4; i++) a[i]  = As[kk][ty*4 + i];
            #pragma unroll
            for (int j = 0; j < 4; j++) bv[j] = Bs[kk][tx*4 + j];
            #pragma unroll
            for (int i = 0; i < 4; i++)
                #pragma unroll
                for (int j = 0; j < 4; j++) acc[i][j] += a[i]*bv[j];
        }
        __syncthreads();
    }
    #pragma unroll
    for (int i = 0; i < 4; i++) {
        int r = rowBase + ty*4 + i;
        float zz  = d_z[r];
        float zz2 = d_z2[r];
        #pragma unroll
        for (int j = 0; j < 4; j++) {
            int c = colBase + tx*4 + j;
            float scale = (c < Cc/2) ? zz : zz2;
            d_xo[(size_t)r*Cc + c] = acc[i][j]*scale;
        }
    }
}

// ---------------- EMA path ---------------------------------------------------
__global__ void k_argmax(const float* __restrict__ score) {
    __shared__ float sv[256];
    __shared__ int   si[256];
    int row = blockIdx.x, tid = threadIdx.x;
    const float* sr = score + (size_t)row * KD;
    float best = -1e30f; int bi = 0;
    for (int j = tid; j < KD; j += 256) {
        float v = sr[j];
        if (v > best) { best = v; bi = j; }
    }
    sv[tid] = best; si[tid] = bi; __syncthreads();
    for (int o = 128; o; o >>= 1) {
        if (tid < o) {
            if (sv[tid+o] > sv[tid] || (sv[tid+o] == sv[tid] && si[tid+o] < si[tid])) {
                sv[tid] = sv[tid+o]; si[tid] = si[tid+o];
            }
        }
        __syncthreads();
    }
    if (tid == 0) d_ind[row] = si[0];
}

__global__ void k_scatter() {
    size_t idx = (size_t)blockIdx.x * blockDim.x + threadIdx.x;
    int i  = (int)(idx >> 8);
    int ch = (int)(idx & 255);
    int code = d_ind[i];
    atomicAdd(&d_sums[(size_t)code*Cc + ch], d_xf[idx]);
    if (ch == 0) atomicAdd(&d_counts[code], 1.0f);
}

__global__ void k_update_codes(const float* __restrict__ uw) {
    __shared__ float red[256];
    int k = blockIdx.x, ch = threadIdx.x;
    float cnt = d_counts[k];
    float em  = d_sums[(size_t)k*Cc + ch] / (cnt + EPS_Z);
    float mv  = uw[(size_t)k*Cc + ch]*RATE + em*(1.0f - RATE);
    d_mnew[(size_t)k*Cc + ch] = mv;
    red[ch] = mv*mv; __syncthreads();
    for (int o = 128; o; o >>= 1) {
        if (ch < o) red[ch] += red[ch+o];
        __syncthreads();
    }
    float inv = 1.0f / fmaxf(sqrtf(red[0]), EPS_NORM);
    float mnv = mv*inv;
    float pv  = d_p[ch];
    d_kk[(size_t)k*(2*Cc) + ch]        = (mnv  > 0.f) ? powf(mnv,  pv) : 0.f;
    d_kk[(size_t)k*(2*Cc) + Cc + ch]   = (-mnv > 0.f) ? powf(-mnv, pv) : 0.f;
}

__global__ void k_kmean() {
    int col = blockIdx.x * 256 + threadIdx.x;   // 0..511
    float s = 0.f;
    for (int r = 0; r < KD; r++) s += d_kk[(size_t)r*(2*Cc) + col];
    d_kmean[col] = s * (1.0f / KD);
}

__global__ void k_bmat() {
    int idx = blockIdx.x * 256 + threadIdx.x;   // 512*256 total
    int r = idx >> 8, j = idx & 255;
    int rr = (j < Cc/2) ? r : (r ^ Cc);
    d_Bmat[(size_t)r*Cc + j] = d_kvfull[(size_t)rr*Cc + j] * (1.0f / (float)Nn);
}

// ---------------- power features + z ----------------------------------------
__global__ void k_powq() {
    size_t idx = (size_t)blockIdx.x * blockDim.x + threadIdx.x;
    int i  = (int)(idx >> 8);
    int ch = (int)(idx & 255);
    float v  = d_xn[idx];
    float pv = d_p[ch];
    float qp = (v  > 0.f) ? powf(v,  pv) : 0.f;
    float qn = (-v > 0.f) ? powf(-v, pv) : 0.f;
    d_qcat[(size_t)i*(2*Cc) + ch]      = qp;
    d_qcat[(size_t)i*(2*Cc) + Cc + ch] = qn;
}

__global__ void k_zrow() {
    int row  = blockIdx.x * 8 + (threadIdx.x >> 5);
    int lane = threadIdx.x & 31;
    const float* q = d_qcat + (size_t)row * (2*Cc);
    float s1 = 0.f, s2 = 0.f;
    for (int r = lane; r < 2*Cc; r += 32) {
        float qv = q[r];
        s1 += qv * d_kmean[r];
        s2 += qv * d_kmean[r ^ Cc];
    }
    #pragma unroll
    for (int o = 16; o; o >>= 1) {
        s1 += __shfl_xor_sync(0xffffffffu, s1, o);
        s2 += __shfl_xor_sync(0xffffffffu, s2, o);
    }
    if (lane == 0) {
        d_z [row] = 1.0f / (s1 + EPS_Z);
        d_z2[row] = 1.0f / (s2 + EPS_Z);
    }
}

// ---------------- depthwise conv + residual + gate ---------------------------
__global__ void k_conv(const float* __restrict__ wgt, const float* __restrict__ bias) {
    size_t idx = (size_t)blockIdx.x * blockDim.x + threadIdx.x;
    int i  = (int)(idx >> 8);
    int ch = (int)(idx & 255);
    int s  = i & (HW - 1);
    int h  = s >> 6, w = s & 63;
    float center = d_xo[idx];
    float acc = bias[ch];
    #pragma unroll
    for (int kh = 0; kh < 3; kh++) {
        int hh = h + kh - 1;
        if (hh < 0 || hh >= Hh) continue;
        #pragma unroll
        for (int kw = 0; kw < 3; kw++) {
            int ww2 = w + kw - 1;
            if (ww2 < 0 || ww2 >= Ww) continue;
            float wv = wgt[ch*9 + kh*3 + kw];
            acc += wv * d_xo[(size_t)(i + (kh-1)*Ww + (kw-1))*Cc + ch];
        }
    }
    d_ot[idx] = (center + acc) * d_g[idx];
}

// ot (B*HW, C) -> out NCHW
__global__ void k_transpose_out(float* __restrict__ out) {
    __shared__ float tile[32][33];
    int b  = blockIdx.z;
    int s0 = blockIdx.x * 32, c0 = blockIdx.y * 32;
    int tx = threadIdx.x, ty = threadIdx.y;
    #pragma unroll
    for (int r = ty; r < 32; r += 8)
        tile[r][tx] = d_ot[((size_t)b*HW + s0 + r)*Cc + c0 + tx];
    __syncthreads();
    #pragma unroll
    for (int r = ty; r < 32; r += 8)
        out[((size_t)(b*Cc + c0 + r))*HW + s0 + tx] = tile[tx][r];
}

// ---------------- launch -----------------------------------------------------
extern "C" void kernel_launch(void* const* d_in, const int* in_sizes, int n_in,
                              void* d_out, int out_size)
{
    const float* x       = (const float*)d_in[0];
    const float* units_w = (const float*)d_in[1];
    const float* power   = (const float*)d_in[2];
    const float* g_w     = (const float*)d_in[3];
    const float* g_b     = (const float*)d_in[4];
    const float* dwc_w   = (const float*)d_in[5];
    const float* dwc_b   = (const float*)d_in[6];

    float* out   = (float*)d_out;                  // (B,C,H,W)
    float* score = (float*)d_out + OUT_ELEMS;      // (N, K)

    k_prep_p<<<1, Cc>>>(power);
    k_zero<<<(KD*Cc + KD + 255)/256, 256>>>();
    k_norm_units<<<KD/8, 256>>>(units_w);

    dim3 tb(32, 8);
    k_transpose_x<<<dim3(HW/32, Cc/32, Bb), tb>>>(x);
    k_rownorm<<<Nn/8, 256>>>();

    // g = xf @ g_w^T + g_b
    k_gemm_g<<<dim3(Cc/64, Nn/64), 256>>>(g_w, g_b);
    // score = xn @ mn0^T
    k_gemm_score<<<dim3(KD/64, Nn/64), 256>>>(score);

    k_argmax<<<Nn, 256>>>(score);
    k_scatter<<<(unsigned)((Nn*(size_t)Cc)/256), 256>>>();
    k_update_codes<<<KD, Cc>>>(units_w);
    k_kmean<<<2, 256>>>();
    k_gemm_kv<<<dim3(Cc/64, (2*Cc)/64), 256>>>();
    k_bmat<<<(2*Cc*Cc)/256, 256>>>();

    k_powq<<<(unsigned)((Nn*(size_t)Cc)/256), 256>>>();
    k_zrow<<<Nn/8, 256>>>();
    k_gemm_xo<<<dim3(Cc/64, Nn/64), 256>>>();

    k_conv<<<(unsigned)((Nn*(size_t)Cc)/256), 256>>>(dwc_w, dwc_b);
    k_transpose_out<<<dim3(HW/32, Cc/32, Bb), tb>>>(out);
}

// round 5
// speedup vs baseline: 2.0338x; 2.0338x over previous
#include <cuda_runtime.h>
#include <cuda_bf16.h>
#include <cstdint>
#include <math.h>

// Problem constants (fixed shapes for this dataset)
#define Bb   8
#define Cc   256
#define Hh   64
#define Ww   64
#define HW   (Hh*Ww)          // 4096
#define Nn   (Bb*HW)          // 32768
#define KD   1024
#define OUT_ELEMS ((size_t)Bb*Cc*HW)   // 8388608

#define EPS_NORM 1e-12f
#define EPS_Z    1e-6f
#define RATE     0.999f

// ---------------- scratch (device globals; no allocation allowed) -----------
__device__ float d_xf  [(size_t)Nn*Cc];
__device__ float d_xn  [(size_t)Nn*Cc];
__device__ float d_g   [(size_t)Nn*Cc];
__device__ float d_xo  [(size_t)Nn*Cc];
__device__ float d_ot  [(size_t)Nn*Cc];
__device__ float d_qcat[(size_t)Nn*2*Cc];
__device__ float d_mn0 [(size_t)KD*Cc];
__device__ float d_mnew[(size_t)KD*Cc];
__device__ float d_kk  [(size_t)KD*2*Cc];
__device__ float d_sums[(size_t)KD*Cc];
__device__ float d_counts[KD];
__device__ int   d_ind [Nn];
__device__ float d_p   [Cc];
__device__ float d_kmean[2*Cc];
__device__ float d_kvfull[(size_t)2*Cc*Cc]; // 512 x 256
__device__ float d_BmatT [(size_t)Cc*2*Cc]; // 256 x 512 (transposed Bmat)
__device__ float d_z [Nn];
__device__ float d_z2[Nn];

__device__ __forceinline__ float to_tf32(float x) {
    float r;
    asm("cvt.rna.tf32.f32 %0, %1;" : "=f"(r) : "f"(x));
    return r;
}

// ---------------- tf32 mma.sync NT GEMM --------------------------------------
// C[M,N2] = A[M,Kd] @ B[N2,Kd]^T
// mode 0: plain   mode 1: + bias[col]   mode 2: * (col<128 ? d_z[row] : d_z2[row])
// Block tile 128x128, K-tile 32, 8 warps (2 x 4), warp tile 64x32.
#define SMPAD 36

__global__ __launch_bounds__(256)
void k_mma_nt(const float* __restrict__ Aptr, const float* __restrict__ Bptr,
              float* __restrict__ Cptr, const float* __restrict__ bias,
              int M, int N2, int Kd, int mode)
{
    __shared__ float As[128*SMPAD];
    __shared__ float Bs[128*SMPAD];
    int tid  = threadIdx.x;
    int lane = tid & 31, wid = tid >> 5;
    int wm = wid >> 2, wn = wid & 3;       // 2 x 4 warp grid
    int gID = lane >> 2, qd = lane & 3;    // mma fragment coords
    const int rowBase = blockIdx.y * 128;
    const int colBase = blockIdx.x * 128;

    float acc[4][4][4];
    #pragma unroll
    for (int i = 0; i < 4; i++)
        #pragma unroll
        for (int j = 0; j < 4; j++)
            #pragma unroll
            for (int t = 0; t < 4; t++) acc[i][j][t] = 0.f;

    for (int k0 = 0; k0 < Kd; k0 += 32) {
        // prefetch gmem -> regs
        float4 ra[4], rb[4];
        #pragma unroll
        for (int i = 0; i < 4; i++) {
            int idx = tid + i*256;
            int r = idx >> 3, q = idx & 7;
            ra[i] = *(const float4*)(Aptr + (size_t)(rowBase + r)*Kd + k0 + q*4);
            rb[i] = *(const float4*)(Bptr + (size_t)(colBase + r)*Kd + k0 + q*4);
        }
        __syncthreads();   // previous k-tile fully consumed
        #pragma unroll
        for (int i = 0; i < 4; i++) {
            int idx = tid + i*256;
            int r = idx >> 3, q = idx & 7;
            float4 va = ra[i], vb = rb[i];
            va.x = to_tf32(va.x); va.y = to_tf32(va.y); va.z = to_tf32(va.z); va.w = to_tf32(va.w);
            vb.x = to_tf32(vb.x); vb.y = to_tf32(vb.y); vb.z = to_tf32(vb.z); vb.w = to_tf32(vb.w);
            *(float4*)(As + r*SMPAD + q*4) = va;
            *(float4*)(Bs + r*SMPAD + q*4) = vb;
        }
        __syncthreads();

        #pragma unroll
        for (int ks = 0; ks < 4; ks++) {
            int kb = ks * 8;
            uint32_t bf[4][2];
            #pragma unroll
            for (int j = 0; j < 4; j++) {
                int n0 = wn*32 + j*8;
                bf[j][0] = __float_as_uint(Bs[(n0 + gID)*SMPAD + kb + qd]);
                bf[j][1] = __float_as_uint(Bs[(n0 + gID)*SMPAD + kb + qd + 4]);
            }
            #pragma unroll
            for (int i = 0; i < 4; i++) {
                int m0 = wm*64 + i*16;
                uint32_t af0 = __float_as_uint(As[(m0 + gID     )*SMPAD + kb + qd]);
                uint32_t af1 = __float_as_uint(As[(m0 + 8 + gID )*SMPAD + kb + qd]);
                uint32_t af2 = __float_as_uint(As[(m0 + gID     )*SMPAD + kb + qd + 4]);
                uint32_t af3 = __float_as_uint(As[(m0 + 8 + gID )*SMPAD + kb + qd + 4]);
                #pragma unroll
                for (int j = 0; j < 4; j++) {
                    asm volatile(
                        "mma.sync.aligned.m16n8k8.row.col.f32.tf32.tf32.f32 "
                        "{%0,%1,%2,%3}, {%4,%5,%6,%7}, {%8,%9}, {%0,%1,%2,%3};"
                        : "+f"(acc[i][j][0]), "+f"(acc[i][j][1]),
                          "+f"(acc[i][j][2]), "+f"(acc[i][j][3])
                        : "r"(af0), "r"(af1), "r"(af2), "r"(af3),
                          "r"(bf[j][0]), "r"(bf[j][1]));
                }
            }
        }
    }

    // epilogue: direct stores (8B per store, full 32B sectors)
    #pragma unroll
    for (int i = 0; i < 4; i++) {
        int r0 = rowBase + wm*64 + i*16 + gID;
        int r1 = r0 + 8;
        float s0 = 1.f, s1 = 1.f;
        if (mode == 2) {
            bool firstHalf = (colBase < Cc/2);
            s0 = firstHalf ? d_z[r0] : d_z2[r0];
            s1 = firstHalf ? d_z[r1] : d_z2[r1];
        }
        #pragma unroll
        for (int j = 0; j < 4; j++) {
            int c0 = colBase + wn*32 + j*8 + 2*qd;
            float v00 = acc[i][j][0], v01 = acc[i][j][1];
            float v10 = acc[i][j][2], v11 = acc[i][j][3];
            if (mode == 1) {
                float b0 = bias[c0], b1 = bias[c0+1];
                v00 += b0; v01 += b1; v10 += b0; v11 += b1;
            } else if (mode == 2) {
                v00 *= s0; v01 *= s0; v10 *= s1; v11 *= s1;
            }
            *(float2*)(Cptr + (size_t)r0*N2 + c0) = make_float2(v00, v01);
            *(float2*)(Cptr + (size_t)r1*N2 + c0) = make_float2(v10, v11);
        }
    }
}

// ---------------- small kernels ---------------------------------------------
__global__ void k_prep_p(const float* __restrict__ power) {
    int c = threadIdx.x;
    float pw = power[c];
    d_p[c] = 1.0f + 4.0f / (1.0f + __expf(-pw));
}

__global__ void k_zero() {
    int idx = blockIdx.x * blockDim.x + threadIdx.x;
    int tot = KD*Cc + KD;
    if (idx < KD*Cc) d_sums[idx] = 0.f;
    else if (idx < tot) d_counts[idx - KD*Cc] = 0.f;
}

__global__ void k_norm_units(const float* __restrict__ uw) {
    int row  = blockIdx.x * 8 + (threadIdx.x >> 5);
    int lane = threadIdx.x & 31;
    const float* r = uw + (size_t)row * Cc;
    float ss = 0.f;
    for (int j = lane; j < Cc; j += 32) { float v = r[j]; ss += v*v; }
    #pragma unroll
    for (int o = 16; o; o >>= 1) ss += __shfl_xor_sync(0xffffffffu, ss, o);
    float inv = 1.0f / fmaxf(sqrtf(ss), EPS_NORM);
    for (int j = lane; j < Cc; j += 32) d_mn0[(size_t)row*Cc + j] = r[j]*inv;
}

// x (B,C,HW) -> xf (B*HW, C)
__global__ void k_transpose_x(const float* __restrict__ x) {
    __shared__ float tile[32][33];
    int b  = blockIdx.z;
    int c0 = blockIdx.y * 32, s0 = blockIdx.x * 32;
    int tx = threadIdx.x, ty = threadIdx.y;
    #pragma unroll
    for (int r = ty; r < 32; r += 8)
        tile[r][tx] = x[((size_t)(b*Cc + c0 + r))*HW + s0 + tx];
    __syncthreads();
    #pragma unroll
    for (int r = ty; r < 32; r += 8)
        d_xf[((size_t)b*HW + s0 + r)*Cc + c0 + tx] = tile[tx][r];
}

__global__ void k_rownorm() {
    int row  = blockIdx.x * 8 + (threadIdx.x >> 5);
    int lane = threadIdx.x & 31;
    const float* r = d_xf + (size_t)row * Cc;
    float ss = 0.f;
    for (int j = lane; j < Cc; j += 32) { float v = r[j]; ss += v*v; }
    #pragma unroll
    for (int o = 16; o; o >>= 1) ss += __shfl_xor_sync(0xffffffffu, ss, o);
    float inv = 1.0f / fmaxf(sqrtf(ss), EPS_NORM);
    for (int j = lane; j < Cc; j += 32) d_xn[(size_t)row*Cc + j] = r[j]*inv;
}

// KVfull[512,256] = kk^T (512x1024) @ mnew (1024x256) — small, fp32
__global__ __launch_bounds__(256)
void k_gemm_kv()
{
    __shared__ float As[16][68];
    __shared__ float Bs[16][68];
    int tid = threadIdx.x;
    int tx = tid & 15, ty = tid >> 4;
    int rowBase = blockIdx.y * 64, colBase = blockIdx.x * 64;
    float acc[4][4] = {};
    for (int k0 = 0; k0 < KD; k0 += 16) {
        #pragma unroll
        for (int e = 0; e < 4; e++) {
            int t = tid + e*256;
            int kk = t >> 6, r = t & 63;
            As[kk][r] = d_kk[(size_t)(k0 + kk)*(2*Cc) + rowBase + r];
        }
        #pragma unroll
        for (int e = 0; e < 4; e++) {
            int t = tid + e*256;
            int kk = t >> 6, c = t & 63;
            Bs[kk][c] = d_mnew[(size_t)(k0 + kk)*Cc + colBase + c];
        }
        __syncthreads();
        #pragma unroll
        for (int kk = 0; kk < 16; kk++) {
            float a[4], bv[4];
            #pragma unroll
            for (int i = 0; i < 4; i++) a[i]  = As[kk][ty*4 + i];
            #pragma unroll
            for (int j = 0; j < 4; j++) bv[j] = Bs[kk][tx*4 + j];
            #pragma unroll
            for (int i = 0; i < 4; i++)
                #pragma unroll
                for (int j = 0; j < 4; j++) acc[i][j] += a[i]*bv[j];
        }
        __syncthreads();
    }
    #pragma unroll
    for (int i = 0; i < 4; i++) {
        int r = rowBase + ty*4 + i;
        #pragma unroll
        for (int j = 0; j < 4; j++)
            d_kvfull[(size_t)r*Cc + colBase + tx*4 + j] = acc[i][j];
    }
}

// ---------------- EMA path ---------------------------------------------------
__global__ void k_argmax(const float* __restrict__ score) {
    __shared__ float sv[256];
    __shared__ int   si[256];
    int row = blockIdx.x, tid = threadIdx.x;
    const float* sr = score + (size_t)row * KD;
    float best = -1e30f; int bi = 0;
    for (int j = tid; j < KD; j += 256) {
        float v = sr[j];
        if (v > best) { best = v; bi = j; }
    }
    sv[tid] = best; si[tid] = bi; __syncthreads();
    for (int o = 128; o; o >>= 1) {
        if (tid < o) {
            if (sv[tid+o] > sv[tid] || (sv[tid+o] == sv[tid] && si[tid+o] < si[tid])) {
                sv[tid] = sv[tid+o]; si[tid] = si[tid+o];
            }
        }
        __syncthreads();
    }
    if (tid == 0) d_ind[row] = si[0];
}

__global__ void k_scatter() {
    size_t idx = (size_t)blockIdx.x * blockDim.x + threadIdx.x;
    int i  = (int)(idx >> 8);
    int ch = (int)(idx & 255);
    int code = d_ind[i];
    atomicAdd(&d_sums[(size_t)code*Cc + ch], d_xf[idx]);
    if (ch == 0) atomicAdd(&d_counts[code], 1.0f);
}

__global__ void k_update_codes(const float* __restrict__ uw) {
    __shared__ float red[256];
    int k = blockIdx.x, ch = threadIdx.x;
    float cnt = d_counts[k];
    float em  = d_sums[(size_t)k*Cc + ch] / (cnt + EPS_Z);
    float mv  = uw[(size_t)k*Cc + ch]*RATE + em*(1.0f - RATE);
    d_mnew[(size_t)k*Cc + ch] = mv;
    red[ch] = mv*mv; __syncthreads();
    for (int o = 128; o; o >>= 1) {
        if (ch < o) red[ch] += red[ch+o];
        __syncthreads();
    }
    float inv = 1.0f / fmaxf(sqrtf(red[0]), EPS_NORM);
    float mnv = mv*inv;
    float pv  = d_p[ch];
    d_kk[(size_t)k*(2*Cc) + ch]        = (mnv  > 0.f) ? powf(mnv,  pv) : 0.f;
    d_kk[(size_t)k*(2*Cc) + Cc + ch]   = (-mnv > 0.f) ? powf(-mnv, pv) : 0.f;
}

__global__ void k_kmean() {
    int col = blockIdx.x * 256 + threadIdx.x;   // 0..511
    float s = 0.f;
    for (int r = 0; r < KD; r++) s += d_kk[(size_t)r*(2*Cc) + col];
    d_kmean[col] = s * (1.0f / KD);
}

// BmatT[j][r] = kvfull[rr][j] / Nn, rr = (j < 128) ? r : (r ^ 256)
__global__ void k_bmatT() {
    int idx = blockIdx.x * 256 + threadIdx.x;   // 512*256 total
    int r = idx >> 8, j = idx & 255;
    int rr = (j < Cc/2) ? r : (r ^ Cc);
    d_BmatT[(size_t)j*(2*Cc) + r] = d_kvfull[(size_t)rr*Cc + j] * (1.0f / (float)Nn);
}

// ---------------- power features + z ----------------------------------------
__global__ void k_powq() {
    size_t idx = (size_t)blockIdx.x * blockDim.x + threadIdx.x;
    int i  = (int)(idx >> 8);
    int ch = (int)(idx & 255);
    float v  = d_xn[idx];
    float pv = d_p[ch];
    float qp = (v  > 0.f) ? powf(v,  pv) : 0.f;
    float qn = (-v > 0.f) ? powf(-v, pv) : 0.f;
    d_qcat[(size_t)i*(2*Cc) + ch]      = qp;
    d_qcat[(size_t)i*(2*Cc) + Cc + ch] = qn;
}

__global__ void k_zrow() {
    int row  = blockIdx.x * 8 + (threadIdx.x >> 5);
    int lane = threadIdx.x & 31;
    const float* q = d_qcat + (size_t)row * (2*Cc);
    float s1 = 0.f, s2 = 0.f;
    for (int r = lane; r < 2*Cc; r += 32) {
        float qv = q[r];
        s1 += qv * d_kmean[r];
        s2 += qv * d_kmean[r ^ Cc];
    }
    #pragma unroll
    for (int o = 16; o; o >>= 1) {
        s1 += __shfl_xor_sync(0xffffffffu, s1, o);
        s2 += __shfl_xor_sync(0xffffffffu, s2, o);
    }
    if (lane == 0) {
        d_z [row] = 1.0f / (s1 + EPS_Z);
        d_z2[row] = 1.0f / (s2 + EPS_Z);
    }
}

// ---------------- depthwise conv + residual + gate ---------------------------
__global__ void k_conv(const float* __restrict__ wgt, const float* __restrict__ bias) {
    size_t idx = (size_t)blockIdx.x * blockDim.x + threadIdx.x;
    int i  = (int)(idx >> 8);
    int ch = (int)(idx & 255);
    int s  = i & (HW - 1);
    int h  = s >> 6, w = s & 63;
    float center = d_xo[idx];
    float acc = bias[ch];
    #pragma unroll
    for (int kh = 0; kh < 3; kh++) {
        int hh = h + kh - 1;
        if (hh < 0 || hh >= Hh) continue;
        #pragma unroll
        for (int kw = 0; kw < 3; kw++) {
            int ww2 = w + kw - 1;
            if (ww2 < 0 || ww2 >= Ww) continue;
            float wv = wgt[ch*9 + kh*3 + kw];
            acc += wv * d_xo[(size_t)(i + (kh-1)*Ww + (kw-1))*Cc + ch];
        }
    }
    d_ot[idx] = (center + acc) * d_g[idx];
}

// ot (B*HW, C) -> out NCHW
__global__ void k_transpose_out(float* __restrict__ out) {
    __shared__ float tile[32][33];
    int b  = blockIdx.z;
    int s0 = blockIdx.x * 32, c0 = blockIdx.y * 32;
    int tx = threadIdx.x, ty = threadIdx.y;
    #pragma unroll
    for (int r = ty; r < 32; r += 8)
        tile[r][tx] = d_ot[((size_t)b*HW + s0 + r)*Cc + c0 + tx];
    __syncthreads();
    #pragma unroll
    for (int r = ty; r < 32; r += 8)
        out[((size_t)(b*Cc + c0 + r))*HW + s0 + tx] = tile[tx][r];
}

// ---------------- launch -----------------------------------------------------
extern "C" void kernel_launch(void* const* d_in, const int* in_sizes, int n_in,
                              void* d_out, int out_size)
{
    const float* x       = (const float*)d_in[0];
    const float* units_w = (const float*)d_in[1];
    const float* power   = (const float*)d_in[2];
    const float* g_w     = (const float*)d_in[3];
    const float* g_b     = (const float*)d_in[4];
    const float* dwc_w   = (const float*)d_in[5];
    const float* dwc_b   = (const float*)d_in[6];

    float* out   = (float*)d_out;                  // (B,C,H,W)
    float* score = (float*)d_out + OUT_ELEMS;      // (N, K)

    // device addresses of scratch globals (host-side symbol lookup; no alloc)
    float *p_xf, *p_xn, *p_g, *p_xo, *p_qcat, *p_mn0, *p_bmatT;
    cudaGetSymbolAddress((void**)&p_xf,    d_xf);
    cudaGetSymbolAddress((void**)&p_xn,    d_xn);
    cudaGetSymbolAddress((void**)&p_g,     d_g);
    cudaGetSymbolAddress((void**)&p_xo,    d_xo);
    cudaGetSymbolAddress((void**)&p_qcat,  d_qcat);
    cudaGetSymbolAddress((void**)&p_mn0,   d_mn0);
    cudaGetSymbolAddress((void**)&p_bmatT, d_BmatT);

    k_prep_p<<<1, Cc>>>(power);
    k_zero<<<(KD*Cc + KD + 255)/256, 256>>>();
    k_norm_units<<<KD/8, 256>>>(units_w);

    dim3 tb(32, 8);
    k_transpose_x<<<dim3(HW/32, Cc/32, Bb), tb>>>(x);
    k_rownorm<<<Nn/8, 256>>>();

    // g = xf @ g_w^T + g_b   (tf32 mma.sync)
    k_mma_nt<<<dim3(Cc/128, Nn/128), 256>>>(p_xf, g_w, p_g, g_b, Nn, Cc, Cc, 1);
    // score = xn @ mn0^T     (tf32 mma.sync)
    k_mma_nt<<<dim3(KD/128, Nn/128), 256>>>(p_xn, p_mn0, score, nullptr, Nn, KD, Cc, 0);

    k_argmax<<<Nn, 256>>>(score);
    k_scatter<<<(unsigned)((Nn*(size_t)Cc)/256), 256>>>();
    k_update_codes<<<KD, Cc>>>(units_w);
    k_kmean<<<2, 256>>>();
    k_gemm_kv<<<dim3(Cc/64, (2*Cc)/64), 256>>>();
    k_bmatT<<<(2*Cc*Cc)/256, 256>>>();

    k_powq<<<(unsigned)((Nn*(size_t)Cc)/256), 256>>>();
    k_zrow<<<Nn/8, 256>>>();
    // xo = qcat @ BmatT^T, scaled by z/z2   (tf32 mma.sync)
    k_mma_nt<<<dim3(Cc/128, Nn/128), 256>>>(p_qcat, p_bmatT, p_xo, nullptr, Nn, Cc, 2*Cc, 2);

    k_conv<<<(unsigned)((Nn*(size_t)Cc)/256), 256>>>(dwc_w, dwc_b);
    k_transpose_out<<<dim3(HW/32, Cc/32, Bb), tb>>>(out);
}

// round 7
// speedup vs baseline: 2.9526x; 1.4518x over previous
#include <cuda_runtime.h>
#include <cuda_fp16.h>
#include <cstdint>
#include <math.h>

// Problem constants (fixed shapes for this dataset)
#define Bb   8
#define Cc   256
#define Hh   64
#define Ww   64
#define HW   (Hh*Ww)          // 4096
#define Nn   (Bb*HW)          // 32768
#define KD   1024
#define OUT_ELEMS ((size_t)Bb*Cc*HW)   // 8388608

#define EPS_NORM 1e-12f
#define EPS_Z    1e-6f
#define RATE     0.999f

// ---------------- scratch (device globals; no allocation allowed) -----------
__device__ float  d_xf  [(size_t)Nn*Cc];
__device__ float  d_xn  [(size_t)Nn*Cc];
__device__ float  d_g   [(size_t)Nn*Cc];
__device__ float  d_xo  [(size_t)Nn*Cc];
__device__ float  d_ot  [(size_t)Nn*Cc];
__device__ __half d_qcat[(size_t)Nn*2*Cc];
__device__ float  d_mn0 [(size_t)KD*Cc];
__device__ float  d_mnew[(size_t)KD*Cc];
__device__ float  d_kk  [(size_t)KD*2*Cc];
__device__ float  d_sums[(size_t)KD*Cc];
__device__ float  d_counts[KD];
__device__ int    d_ind [Nn];
__device__ unsigned long long d_best[Nn];
__device__ float  d_p   [Cc];
__device__ float  d_kmean[2*Cc];
__device__ float  d_kvfull[(size_t)2*Cc*Cc];  // 512 x 256
__device__ __half d_BmatTh[(size_t)Cc*2*Cc];  // 256 x 512 (transposed, NO 1/N)
__device__ float  d_z [Nn];
__device__ float  d_z2[Nn];

// ---------------- fp16 mma.sync NT GEMM --------------------------------------
// C[M,N2] = A[M,Kd] @ B[N2,Kd]^T  (fp16 inputs in smem, fp32 accumulate)
// MODE 0: score (+fused argmax atomics)  MODE 1: + bias[col]
// MODE 2: * (col<128 ? d_z[row] : d_z2[row]) * escale
// Block tile 128x128, K-tile 32, 8 warps (2 x 4), warp tile 64x32.
#define HSTRIDE 40   // halves per smem row (even => half2-aligned)

template<int MODE, bool AH, bool BH>
__global__ __launch_bounds__(256)
void k_mma_fp16(const void* __restrict__ Ain, const void* __restrict__ Bin,
                float* __restrict__ Cptr, const float* __restrict__ bias,
                int N2, int Kd, float escale)
{
    __shared__ __half As[128*HSTRIDE];
    __shared__ __half Bs[128*HSTRIDE];
    int tid  = threadIdx.x;
    int lane = tid & 31, wid = tid >> 5;
    int wm = wid >> 2, wn = wid & 3;       // 2 x 4 warp grid
    int gID = lane >> 2, qd = lane & 3;    // mma fragment coords
    const int rowBase = blockIdx.y * 128;
    const int colBase = blockIdx.x * 128;

    float acc[4][4][4];
    #pragma unroll
    for (int i = 0; i < 4; i++)
        #pragma unroll
        for (int j = 0; j < 4; j++)
            #pragma unroll
            for (int t = 0; t < 4; t++) acc[i][j][t] = 0.f;

    for (int k0 = 0; k0 < Kd; k0 += 32) {
        // ---- prefetch gmem -> regs ----
        float4 fa[4], fb[4];
        uint4  ha[2], hb[2];
        if (!AH) {
            const float* Ap = (const float*)Ain;
            #pragma unroll
            for (int i = 0; i < 4; i++) {
                int idx = tid + i*256;
                int r = idx >> 3, q = idx & 7;
                fa[i] = *(const float4*)(Ap + (size_t)(rowBase + r)*Kd + k0 + q*4);
            }
        } else {
            const __half* Ap = (const __half*)Ain;
            #pragma unroll
            for (int i = 0; i < 2; i++) {
                int idx = tid + i*256;
                int r = idx >> 2, q = idx & 3;
                ha[i] = *(const uint4*)(Ap + (size_t)(rowBase + r)*Kd + k0 + q*8);
            }
        }
        if (!BH) {
            const float* Bp = (const float*)Bin;
            #pragma unroll
            for (int i = 0; i < 4; i++) {
                int idx = tid + i*256;
                int r = idx >> 3, q = idx & 7;
                fb[i] = *(const float4*)(Bp + (size_t)(colBase + r)*Kd + k0 + q*4);
            }
        } else {
            const __half* Bp = (const __half*)Bin;
            #pragma unroll
            for (int i = 0; i < 2; i++) {
                int idx = tid + i*256;
                int r = idx >> 2, q = idx & 3;
                hb[i] = *(const uint4*)(Bp + (size_t)(colBase + r)*Kd + k0 + q*8);
            }
        }
        __syncthreads();   // previous k-tile fully consumed
        if (!AH) {
            #pragma unroll
            for (int i = 0; i < 4; i++) {
                int idx = tid + i*256;
                int r = idx >> 3, q = idx & 7;
                __half2 h0 = __floats2half2_rn(fa[i].x, fa[i].y);
                __half2 h1 = __floats2half2_rn(fa[i].z, fa[i].w);
                *(__half2*)(As + r*HSTRIDE + q*4)     = h0;
                *(__half2*)(As + r*HSTRIDE + q*4 + 2) = h1;
            }
        } else {
            #pragma unroll
            for (int i = 0; i < 2; i++) {
                int idx = tid + i*256;
                int r = idx >> 2, q = idx & 3;
                *(uint4*)(As + r*HSTRIDE + q*8) = ha[i];
            }
        }
        if (!BH) {
            #pragma unroll
            for (int i = 0; i < 4; i++) {
                int idx = tid + i*256;
                int r = idx >> 3, q = idx & 7;
                __half2 h0 = __floats2half2_rn(fb[i].x, fb[i].y);
                __half2 h1 = __floats2half2_rn(fb[i].z, fb[i].w);
                *(__half2*)(Bs + r*HSTRIDE + q*4)     = h0;
                *(__half2*)(Bs + r*HSTRIDE + q*4 + 2) = h1;
            }
        } else {
            #pragma unroll
            for (int i = 0; i < 2; i++) {
                int idx = tid + i*256;
                int r = idx >> 2, q = idx & 3;
                *(uint4*)(Bs + r*HSTRIDE + q*8) = hb[i];
            }
        }
        __syncthreads();

        // ---- MMA: 2 k16 steps ----
        #pragma unroll
        for (int ks = 0; ks < 2; ks++) {
            int kb = ks * 16;
            uint32_t bf[4][2];
            #pragma unroll
            for (int j = 0; j < 4; j++) {
                int n0 = wn*32 + j*8 + gID;
                bf[j][0] = *(const uint32_t*)(Bs + n0*HSTRIDE + kb + 2*qd);
                bf[j][1] = *(const uint32_t*)(Bs + n0*HSTRIDE + kb + 8 + 2*qd);
            }
            #pragma unroll
            for (int i = 0; i < 4; i++) {
                int m0 = wm*64 + i*16;
                uint32_t a0 = *(const uint32_t*)(As + (m0 + gID    )*HSTRIDE + kb + 2*qd);
                uint32_t a1 = *(const uint32_t*)(As + (m0 + 8 + gID)*HSTRIDE + kb + 2*qd);
                uint32_t a2 = *(const uint32_t*)(As + (m0 + gID    )*HSTRIDE + kb + 8 + 2*qd);
                uint32_t a3 = *(const uint32_t*)(As + (m0 + 8 + gID)*HSTRIDE + kb + 8 + 2*qd);
                #pragma unroll
                for (int j = 0; j < 4; j++) {
                    asm volatile(
                        "mma.sync.aligned.m16n8k16.row.col.f32.f16.f16.f32 "
                        "{%0,%1,%2,%3}, {%4,%5,%6,%7}, {%8,%9}, {%0,%1,%2,%3};"
                        : "+f"(acc[i][j][0]), "+f"(acc[i][j][1]),
                          "+f"(acc[i][j][2]), "+f"(acc[i][j][3])
                        : "r"(a0), "r"(a1), "r"(a2), "r"(a3),
                          "r"(bf[j][0]), "r"(bf[j][1]));
                }
            }
        }
    }

    // ---- epilogue ----
    #pragma unroll
    for (int i = 0; i < 4; i++) {
        int r0 = rowBase + wm*64 + i*16 + gID;
        int r1 = r0 + 8;
        float s0 = 1.f, s1 = 1.f;
        if (MODE == 2) {
            bool firstHalf = (colBase < Cc/2);
            s0 = (firstHalf ? d_z[r0] : d_z2[r0]) * escale;
            s1 = (firstHalf ? d_z[r1] : d_z2[r1]) * escale;
        }
        unsigned long long best0 = 0ull, best1 = 0ull;
        #pragma unroll
        for (int j = 0; j < 4; j++) {
            int c0 = colBase + wn*32 + j*8 + 2*qd;
            float v00 = acc[i][j][0], v01 = acc[i][j][1];
            float v10 = acc[i][j][2], v11 = acc[i][j][3];
            if (MODE == 1) {
                float b0 = bias[c0], b1 = bias[c0+1];
                v00 += b0; v01 += b1; v10 += b0; v11 += b1;
            } else if (MODE == 2) {
                v00 *= s0; v01 *= s0; v10 *= s1; v11 *= s1;
            }
            *(float2*)(Cptr + (size_t)r0*N2 + c0) = make_float2(v00, v01);
            *(float2*)(Cptr + (size_t)r1*N2 + c0) = make_float2(v10, v11);
            if (MODE == 0) {
                // pack (monotonic float key << 32) | (KD-1-col); ties -> lowest col
                uint32_t k00 = __float_as_uint(v00); k00 ^= (k00 & 0x80000000u) ? 0xFFFFFFFFu : 0x80000000u;
                uint32_t k01 = __float_as_uint(v01); k01 ^= (k01 & 0x80000000u) ? 0xFFFFFFFFu : 0x80000000u;
                uint32_t k10 = __float_as_uint(v10); k10 ^= (k10 & 0x80000000u) ? 0xFFFFFFFFu : 0x80000000u;
                uint32_t k11 = __float_as_uint(v11); k11 ^= (k11 & 0x80000000u) ? 0xFFFFFFFFu : 0x80000000u;
                unsigned long long p00 = ((unsigned long long)k00 << 32) | (uint32_t)(KD-1-c0);
                unsigned long long p01 = ((unsigned long long)k01 << 32) | (uint32_t)(KD-2-c0);
                unsigned long long p10 = ((unsigned long long)k10 << 32) | (uint32_t)(KD-1-c0);
                unsigned long long p11 = ((unsigned long long)k11 << 32) | (uint32_t)(KD-2-c0);
                if (p01 > p00) p00 = p01;
                if (p11 > p10) p10 = p11;
                if (p00 > best0) best0 = p00;
                if (p10 > best1) best1 = p10;
            }
        }
        if (MODE == 0) {
            // reduce across qd lanes (lane bits 0..1)
            #pragma unroll
            for (int o = 1; o <= 2; o <<= 1) {
                unsigned long long t0 = __shfl_xor_sync(0xffffffffu, best0, o);
                unsigned long long t1 = __shfl_xor_sync(0xffffffffu, best1, o);
                if (t0 > best0) best0 = t0;
                if (t1 > best1) best1 = t1;
            }
            if (qd == 0) {
                atomicMax(&d_best[r0], best0);
                atomicMax(&d_best[r1], best1);
            }
        }
    }
}

// ---------------- small kernels ---------------------------------------------
__global__ void k_prep_p(const float* __restrict__ power) {
    int c = threadIdx.x;
    float pw = power[c];
    d_p[c] = 1.0f + 4.0f / (1.0f + __expf(-pw));
}

__global__ void k_zero() {
    int idx = blockIdx.x * blockDim.x + threadIdx.x;
    int tot = KD*Cc + KD;
    if (idx < KD*Cc) d_sums[idx] = 0.f;
    else if (idx < tot) d_counts[idx - KD*Cc] = 0.f;
}

__global__ void k_zero_best() {
    int idx = blockIdx.x * blockDim.x + threadIdx.x;
    d_best[idx] = 0ull;
}

__global__ void k_extract_ind() {
    int idx = blockIdx.x * blockDim.x + threadIdx.x;
    d_ind[idx] = KD - 1 - (int)(uint32_t)(d_best[idx] & 0xFFFFFFFFull);
}

__global__ void k_norm_units(const float* __restrict__ uw) {
    int row  = blockIdx.x * 8 + (threadIdx.x >> 5);
    int lane = threadIdx.x & 31;
    const float* r = uw + (size_t)row * Cc;
    float ss = 0.f;
    for (int j = lane; j < Cc; j += 32) { float v = r[j]; ss += v*v; }
    #pragma unroll
    for (int o = 16; o; o >>= 1) ss += __shfl_xor_sync(0xffffffffu, ss, o);
    float inv = 1.0f / fmaxf(sqrtf(ss), EPS_NORM);
    for (int j = lane; j < Cc; j += 32) d_mn0[(size_t)row*Cc + j] = r[j]*inv;
}

// x (B,C,HW) -> xf (B*HW, C)
__global__ void k_transpose_x(const float* __restrict__ x) {
    __shared__ float tile[32][33];
    int b  = blockIdx.z;
    int c0 = blockIdx.y * 32, s0 = blockIdx.x * 32;
    int tx = threadIdx.x, ty = threadIdx.y;
    #pragma unroll
    for (int r = ty; r < 32; r += 8)
        tile[r][tx] = x[((size_t)(b*Cc + c0 + r))*HW + s0 + tx];
    __syncthreads();
    #pragma unroll
    for (int r = ty; r < 32; r += 8)
        d_xf[((size_t)b*HW + s0 + r)*Cc + c0 + tx] = tile[tx][r];
}

__global__ void k_rownorm() {
    int row  = blockIdx.x * 8 + (threadIdx.x >> 5);
    int lane = threadIdx.x & 31;
    const float* r = d_xf + (size_t)row * Cc;
    float ss = 0.f;
    for (int j = lane; j < Cc; j += 32) { float v = r[j]; ss += v*v; }
    #pragma unroll
    for (int o = 16; o; o >>= 1) ss += __shfl_xor_sync(0xffffffffu, ss, o);
    float inv = 1.0f / fmaxf(sqrtf(ss), EPS_NORM);
    for (int j = lane; j < Cc; j += 32) d_xn[(size_t)row*Cc + j] = r[j]*inv;
}

// KVfull[512,256] = kk^T (512x1024) @ mnew (1024x256) — small, fp32
__global__ __launch_bounds__(256)
void k_gemm_kv()
{
    __shared__ float As[16][68];
    __shared__ float Bs[16][68];
    int tid = threadIdx.x;
    int tx = tid & 15, ty = tid >> 4;
    int rowBase = blockIdx.y * 64, colBase = blockIdx.x * 64;
    float acc[4][4] = {};
    for (int k0 = 0; k0 < KD; k0 += 16) {
        #pragma unroll
        for (int e = 0; e < 4; e++) {
            int t = tid + e*256;
            int kk = t >> 6, r = t & 63;
            As[kk][r] = d_kk[(size_t)(k0 + kk)*(2*Cc) + rowBase + r];
        }
        #pragma unroll
        for (int e = 0; e < 4; e++) {
            int t = tid + e*256;
            int kk = t >> 6, c = t & 63;
            Bs[kk][c] = d_mnew[(size_t)(k0 + kk)*Cc + colBase + c];
        }
        __syncthreads();
        #pragma unroll
        for (int kk = 0; kk < 16; kk++) {
            float a[4], bv[4];
            #pragma unroll
            for (int i = 0; i < 4; i++) a[i]  = As[kk][ty*4 + i];
            #pragma unroll
            for (int j = 0; j < 4; j++) bv[j] = Bs[kk][tx*4 + j];
            #pragma unroll
            for (int i = 0; i < 4; i++)
                #pragma unroll
                for (int j = 0; j < 4; j++) acc[i][j] += a[i]*bv[j];
        }
        __syncthreads();
    }
    #pragma unroll
    for (int i = 0; i < 4; i++) {
        int r = rowBase + ty*4 + i;
        #pragma unroll
        for (int j = 0; j < 4; j++)
            d_kvfull[(size_t)r*Cc + colBase + tx*4 + j] = acc[i][j];
    }
}

// ---------------- EMA path ---------------------------------------------------
__global__ void k_scatter() {
    size_t idx = (size_t)blockIdx.x * blockDim.x + threadIdx.x;
    int i  = (int)(idx >> 8);
    int ch = (int)(idx & 255);
    int code = d_ind[i];
    atomicAdd(&d_sums[(size_t)code*Cc + ch], d_xf[idx]);
    if (ch == 0) atomicAdd(&d_counts[code], 1.0f);
}

__global__ void k_update_codes(const float* __restrict__ uw) {
    __shared__ float red[256];
    int k = blockIdx.x, ch = threadIdx.x;
    float cnt = d_counts[k];
    float em  = d_sums[(size_t)k*Cc + ch] / (cnt + EPS_Z);
    float mv  = uw[(size_t)k*Cc + ch]*RATE + em*(1.0f - RATE);
    d_mnew[(size_t)k*Cc + ch] = mv;
    red[ch] = mv*mv; __syncthreads();
    for (int o = 128; o; o >>= 1) {
        if (ch < o) red[ch] += red[ch+o];
        __syncthreads();
    }
    float inv = 1.0f / fmaxf(sqrtf(red[0]), EPS_NORM);
    float mnv = mv*inv;
    float pv  = d_p[ch];
    d_kk[(size_t)k*(2*Cc) + ch]        = (mnv  > 0.f) ? powf(mnv,  pv) : 0.f;
    d_kk[(size_t)k*(2*Cc) + Cc + ch]   = (-mnv > 0.f) ? powf(-mnv, pv) : 0.f;
}

__global__ void k_kmean() {
    int col = blockIdx.x * 256 + threadIdx.x;   // 0..511
    float s = 0.f;
    for (int r = 0; r < KD; r++) s += d_kk[(size_t)r*(2*Cc) + col];
    d_kmean[col] = s * (1.0f / KD);
}

// BmatTh[j][r] = kvfull[rr][j]  (fp16, NO 1/N factor), rr = (j<128) ? r : r^256
__global__ void k_bmatT() {
    int idx = blockIdx.x * 256 + threadIdx.x;   // 512*256 total
    int r = idx >> 8, j = idx & 255;
    int rr = (j < Cc/2) ? r : (r ^ Cc);
    d_BmatTh[(size_t)j*(2*Cc) + r] = __float2half(d_kvfull[(size_t)rr*Cc + j]);
}

// ---------------- fused power features + z (one warp per row) ----------------
__device__ __forceinline__ float fpow(float v, float p) {
    return (v > 0.f) ? exp2f(p * __log2f(v)) : 0.f;
}

__global__ void k_powz() {
    int row  = blockIdx.x * 8 + (threadIdx.x >> 5);
    int lane = threadIdx.x & 31;
    const float* xr = d_xn + (size_t)row * Cc;
    __half* qr = d_qcat + (size_t)row * (2*Cc);
    float s1 = 0.f, s2 = 0.f;
    #pragma unroll
    for (int t = 0; t < 8; t++) {
        int c = lane + t*32;
        float v  = xr[c];
        float pv = d_p[c];
        float qp = fpow(v, pv);
        float qn = fpow(-v, pv);
        qr[c]      = __float2half(qp);
        qr[Cc + c] = __float2half(qn);
        float k1 = d_kmean[c], k2 = d_kmean[Cc + c];
        s1 += qp*k1 + qn*k2;
        s2 += qn*k1 + qp*k2;
    }
    #pragma unroll
    for (int o = 16; o; o >>= 1) {
        s1 += __shfl_xor_sync(0xffffffffu, s1, o);
        s2 += __shfl_xor_sync(0xffffffffu, s2, o);
    }
    if (lane == 0) {
        d_z [row] = 1.0f / (s1 + EPS_Z);
        d_z2[row] = 1.0f / (s2 + EPS_Z);
    }
}

// ---------------- depthwise conv + residual + gate ---------------------------
__global__ void k_conv(const float* __restrict__ wgt, const float* __restrict__ bias) {
    size_t idx = (size_t)blockIdx.x * blockDim.x + threadIdx.x;
    int i  = (int)(idx >> 8);
    int ch = (int)(idx & 255);
    int s  = i & (HW - 1);
    int h  = s >> 6, w = s & 63;
    float center = d_xo[idx];
    float acc = bias[ch];
    #pragma unroll
    for (int kh = 0; kh < 3; kh++) {
        int hh = h + kh - 1;
        if (hh < 0 || hh >= Hh) continue;
        #pragma unroll
        for (int kw = 0; kw < 3; kw++) {
            int ww2 = w + kw - 1;
            if (ww2 < 0 || ww2 >= Ww) continue;
            float wv = wgt[ch*9 + kh*3 + kw];
            acc += wv * d_xo[(size_t)(i + (kh-1)*Ww + (kw-1))*Cc + ch];
        }
    }
    d_ot[idx] = (center + acc) * d_g[idx];
}

// ot (B*HW, C) -> out NCHW
__global__ void k_transpose_out(float* __restrict__ out) {
    __shared__ float tile[32][33];
    int b  = blockIdx.z;
    int s0 = blockIdx.x * 32, c0 = blockIdx.y * 32;
    int tx = threadIdx.x, ty = threadIdx.y;
    #pragma unroll
    for (int r = ty; r < 32; r += 8)
        tile[r][tx] = d_ot[((size_t)b*HW + s0 + r)*Cc + c0 + tx];
    __syncthreads();
    #pragma unroll
    for (int r = ty; r < 32; r += 8)
        out[((size_t)(b*Cc + c0 + r))*HW + s0 + tx] = tile[tx][r];
}

// ---------------- launch -----------------------------------------------------
extern "C" void kernel_launch(void* const* d_in, const int* in_sizes, int n_in,
                              void* d_out, int out_size)
{
    const float* x       = (const float*)d_in[0];
    const float* units_w = (const float*)d_in[1];
    const float* power   = (const float*)d_in[2];
    const float* g_w     = (const float*)d_in[3];
    const float* g_b     = (const float*)d_in[4];
    const float* dwc_w   = (const float*)d_in[5];
    const float* dwc_b   = (const float*)d_in[6];

    float* out   = (float*)d_out;                  // (B,C,H,W)
    float* score = (float*)d_out + OUT_ELEMS;      // (N, K)

    // device addresses of scratch globals
    void *p_xf, *p_xn, *p_g, *p_xo, *p_qcat, *p_mn0, *p_bmatTh;
    cudaGetSymbolAddress(&p_xf,     d_xf);
    cudaGetSymbolAddress(&p_xn,     d_xn);
    cudaGetSymbolAddress(&p_g,      d_g);
    cudaGetSymbolAddress(&p_xo,     d_xo);
    cudaGetSymbolAddress(&p_qcat,   d_qcat);
    cudaGetSymbolAddress(&p_mn0,    d_mn0);
    cudaGetSymbolAddress(&p_bmatTh, d_BmatTh);

    k_prep_p<<<1, Cc>>>(power);
    k_zero<<<(KD*Cc + KD + 255)/256, 256>>>();
    k_zero_best<<<Nn/256, 256>>>();
    k_norm_units<<<KD/8, 256>>>(units_w);

    dim3 tb(32, 8);
    k_transpose_x<<<dim3(HW/32, Cc/32, Bb), tb>>>(x);
    k_rownorm<<<Nn/8, 256>>>();

    // g = xf @ g_w^T + g_b   (fp16 mma)
    k_mma_fp16<1,false,false><<<dim3(Cc/128, Nn/128), 256>>>(
        p_xf, g_w, (float*)p_g, g_b, Cc, Cc, 1.f);
    // score = xn @ mn0^T     (fp16 mma, fused argmax)
    k_mma_fp16<0,false,false><<<dim3(KD/128, Nn/128), 256>>>(
        p_xn, p_mn0, score, nullptr, KD, Cc, 1.f);
    k_extract_ind<<<Nn/256, 256>>>();

    k_scatter<<<(unsigned)((Nn*(size_t)Cc)/256), 256>>>();
    k_update_codes<<<KD, Cc>>>(units_w);
    k_kmean<<<2, 256>>>();
    k_gemm_kv<<<dim3(Cc/64, (2*Cc)/64), 256>>>();
    k_bmatT<<<(2*Cc*Cc)/256, 256>>>();

    k_powz<<<Nn/8, 256>>>();
    // xo = qcat @ BmatTh^T * z/N   (fp16 mma)
    k_mma_fp16<2,true,true><<<dim3(Cc/128, Nn/128), 256>>>(
        p_qcat, p_bmatTh, (float*)p_xo, nullptr, Cc, 2*Cc, 1.0f/(float)Nn);

    k_conv<<<(unsigned)((Nn*(size_t)Cc)/256), 256>>>(dwc_w, dwc_b);
    k_transpose_out<<<dim3(HW/32, Cc/32, Bb), tb>>>(out);
}

// round 8
// speedup vs baseline: 3.4824x; 1.1794x over previous
#include <cuda_runtime.h>
#include <cuda_fp16.h>
#include <cstdint>
#include <math.h>

// Problem constants (fixed shapes for this dataset)
#define Bb   8
#define Cc   256
#define Hh   64
#define Ww   64
#define HW   (Hh*Ww)          // 4096
#define Nn   (Bb*HW)          // 32768
#define KD   1024
#define OUT_ELEMS ((size_t)Bb*Cc*HW)   // 8388608

#define EPS_NORM 1e-12f
#define EPS_Z    1e-6f
#define RATE     0.999f

// ---------------- scratch (device globals; no allocation allowed) -----------
__device__ float  d_xf  [(size_t)Nn*Cc];
__device__ __half d_xfh [(size_t)Nn*Cc];
__device__ float  d_xn  [(size_t)Nn*Cc];
__device__ __half d_xnh [(size_t)Nn*Cc];
__device__ float  d_g   [(size_t)Nn*Cc];
__device__ float  d_xo  [(size_t)Nn*Cc];
__device__ __half d_qcat[(size_t)Nn*2*Cc];
__device__ __half d_mn0h[(size_t)KD*Cc];
__device__ __half d_gwh [(size_t)Cc*Cc];
__device__ float  d_mnew[(size_t)KD*Cc];
__device__ float  d_kk  [(size_t)KD*2*Cc];
__device__ float  d_sums[(size_t)KD*Cc];
__device__ float  d_counts[KD];
__device__ int    d_ind [Nn];
__device__ unsigned long long d_best[Nn];
__device__ float  d_p   [Cc];
__device__ float  d_kmean[2*Cc];
__device__ float  d_kvfull[(size_t)2*Cc*Cc];  // 512 x 256
__device__ __half d_BmatTh[(size_t)Cc*2*Cc];  // 256 x 512 (transposed, NO 1/N)
__device__ float  d_z [Nn];
__device__ float  d_z2[Nn];

// ---------------- cp.async helpers -------------------------------------------
__device__ __forceinline__ void cp_async16(void* smem_dst, const void* gsrc) {
    uint32_t s = (uint32_t)__cvta_generic_to_shared(smem_dst);
    asm volatile("cp.async.cg.shared.global [%0], [%1], 16;" :: "r"(s), "l"(gsrc));
}
#define CP_COMMIT() asm volatile("cp.async.commit_group;" ::: "memory")
#define CP_WAIT(n)  asm volatile("cp.async.wait_group %0;" :: "n"(n) : "memory")

// ---------------- fp16 mma.sync NT GEMM (cp.async double-buffered) ----------
// C[M,N2] = A[M,Kd] @ B[N2,Kd]^T  (fp16 gmem operands, fp32 accumulate)
// MODE 0: score (+fused argmax atomics)  MODE 1: + bias[col]
// MODE 2: * (col<128 ? d_z[row] : d_z2[row]) * escale
// Block tile 128x128, K-tile 32, 8 warps (2 x 4), warp tile 64x32.
#define HSTRIDE 40   // halves per smem row (80B, 16B-aligned)

template<int MODE>
__global__ __launch_bounds__(256)
void k_mma_fp16(const __half* __restrict__ A, const __half* __restrict__ B,
                float* __restrict__ Cptr, const float* __restrict__ bias,
                int N2, int Kd, float escale)
{
    __shared__ __half As[2][128*HSTRIDE];
    __shared__ __half Bs[2][128*HSTRIDE];
    int tid  = threadIdx.x;
    int lane = tid & 31, wid = tid >> 5;
    int wm = wid >> 2, wn = wid & 3;       // 2 x 4 warp grid
    int gID = lane >> 2, qd = lane & 3;    // mma fragment coords
    const int rowBase = blockIdx.y * 128;
    const int colBase = blockIdx.x * 128;
    const __half* Ab = A + (size_t)rowBase * Kd;
    const __half* Bb2 = B + (size_t)colBase * Kd;

    float acc[4][4][4];
    #pragma unroll
    for (int i = 0; i < 4; i++)
        #pragma unroll
        for (int j = 0; j < 4; j++)
            #pragma unroll
            for (int t = 0; t < 4; t++) acc[i][j][t] = 0.f;

    const int nKT = Kd >> 5;

    // prologue: stage 0
    #pragma unroll
    for (int e = 0; e < 2; e++) {
        int idx = tid + e*256;
        int r = idx >> 2, q = idx & 3;
        cp_async16(&As[0][r*HSTRIDE + q*8], Ab + (size_t)r*Kd + q*8);
        cp_async16(&Bs[0][r*HSTRIDE + q*8], Bb2 + (size_t)r*Kd + q*8);
    }
    CP_COMMIT();

    for (int kt = 0; kt < nKT; kt++) {
        int st = kt & 1;
        if (kt + 1 < nKT) {
            int ns = (kt + 1) & 1;
            int koff = (kt + 1) * 32;
            #pragma unroll
            for (int e = 0; e < 2; e++) {
                int idx = tid + e*256;
                int r = idx >> 2, q = idx & 3;
                cp_async16(&As[ns][r*HSTRIDE + q*8], Ab + (size_t)r*Kd + koff + q*8);
                cp_async16(&Bs[ns][r*HSTRIDE + q*8], Bb2 + (size_t)r*Kd + koff + q*8);
            }
            CP_COMMIT();
            CP_WAIT(1);
        } else {
            CP_WAIT(0);
        }
        __syncthreads();

        const __half* Acur = As[st];
        const __half* Bcur = Bs[st];
        #pragma unroll
        for (int ks = 0; ks < 2; ks++) {
            int kb = ks * 16;
            uint32_t bf[4][2];
            #pragma unroll
            for (int j = 0; j < 4; j++) {
                int n0 = wn*32 + j*8 + gID;
                bf[j][0] = *(const uint32_t*)(Bcur + n0*HSTRIDE + kb + 2*qd);
                bf[j][1] = *(const uint32_t*)(Bcur + n0*HSTRIDE + kb + 8 + 2*qd);
            }
            #pragma unroll
            for (int i = 0; i < 4; i++) {
                int m0 = wm*64 + i*16;
                uint32_t a0 = *(const uint32_t*)(Acur + (m0 + gID    )*HSTRIDE + kb + 2*qd);
                uint32_t a1 = *(const uint32_t*)(Acur + (m0 + 8 + gID)*HSTRIDE + kb + 2*qd);
                uint32_t a2 = *(const uint32_t*)(Acur + (m0 + gID    )*HSTRIDE + kb + 8 + 2*qd);
                uint32_t a3 = *(const uint32_t*)(Acur + (m0 + 8 + gID)*HSTRIDE + kb + 8 + 2*qd);
                #pragma unroll
                for (int j = 0; j < 4; j++) {
                    asm volatile(
                        "mma.sync.aligned.m16n8k16.row.col.f32.f16.f16.f32 "
                        "{%0,%1,%2,%3}, {%4,%5,%6,%7}, {%8,%9}, {%0,%1,%2,%3};"
                        : "+f"(acc[i][j][0]), "+f"(acc[i][j][1]),
                          "+f"(acc[i][j][2]), "+f"(acc[i][j][3])
                        : "r"(a0), "r"(a1), "r"(a2), "r"(a3),
                          "r"(bf[j][0]), "r"(bf[j][1]));
                }
            }
        }
        __syncthreads();
    }

    // ---- epilogue ----
    #pragma unroll
    for (int i = 0; i < 4; i++) {
        int r0 = rowBase + wm*64 + i*16 + gID;
        int r1 = r0 + 8;
        float s0 = 1.f, s1 = 1.f;
        if (MODE == 2) {
            bool firstHalf = (colBase < Cc/2);
            s0 = (firstHalf ? d_z[r0] : d_z2[r0]) * escale;
            s1 = (firstHalf ? d_z[r1] : d_z2[r1]) * escale;
        }
        unsigned long long best0 = 0ull, best1 = 0ull;
        #pragma unroll
        for (int j = 0; j < 4; j++) {
            int c0 = colBase + wn*32 + j*8 + 2*qd;
            float v00 = acc[i][j][0], v01 = acc[i][j][1];
            float v10 = acc[i][j][2], v11 = acc[i][j][3];
            if (MODE == 1) {
                float b0 = bias[c0], b1 = bias[c0+1];
                v00 += b0; v01 += b1; v10 += b0; v11 += b1;
            } else if (MODE == 2) {
                v00 *= s0; v01 *= s0; v10 *= s1; v11 *= s1;
            }
            *(float2*)(Cptr + (size_t)r0*N2 + c0) = make_float2(v00, v01);
            *(float2*)(Cptr + (size_t)r1*N2 + c0) = make_float2(v10, v11);
            if (MODE == 0) {
                uint32_t k00 = __float_as_uint(v00); k00 ^= (k00 & 0x80000000u) ? 0xFFFFFFFFu : 0x80000000u;
                uint32_t k01 = __float_as_uint(v01); k01 ^= (k01 & 0x80000000u) ? 0xFFFFFFFFu : 0x80000000u;
                uint32_t k10 = __float_as_uint(v10); k10 ^= (k10 & 0x80000000u) ? 0xFFFFFFFFu : 0x80000000u;
                uint32_t k11 = __float_as_uint(v11); k11 ^= (k11 & 0x80000000u) ? 0xFFFFFFFFu : 0x80000000u;
                unsigned long long p00 = ((unsigned long long)k00 << 32) | (uint32_t)(KD-1-c0);
                unsigned long long p01 = ((unsigned long long)k01 << 32) | (uint32_t)(KD-2-c0);
                unsigned long long p10 = ((unsigned long long)k10 << 32) | (uint32_t)(KD-1-c0);
                unsigned long long p11 = ((unsigned long long)k11 << 32) | (uint32_t)(KD-2-c0);
                if (p01 > p00) p00 = p01;
                if (p11 > p10) p10 = p11;
                if (p00 > best0) best0 = p00;
                if (p10 > best1) best1 = p10;
            }
        }
        if (MODE == 0) {
            #pragma unroll
            for (int o = 1; o <= 2; o <<= 1) {
                unsigned long long t0 = __shfl_xor_sync(0xffffffffu, best0, o);
                unsigned long long t1 = __shfl_xor_sync(0xffffffffu, best1, o);
                if (t0 > best0) best0 = t0;
                if (t1 > best1) best1 = t1;
            }
            if (qd == 0) {
                atomicMax(&d_best[r0], best0);
                atomicMax(&d_best[r1], best1);
            }
        }
    }
}

// ---------------- small kernels ---------------------------------------------
__global__ void k_prep_p(const float* __restrict__ power) {
    int c = threadIdx.x;
    float pw = power[c];
    d_p[c] = 1.0f + 4.0f / (1.0f + __expf(-pw));
}

__global__ void k_zero() {
    int idx = blockIdx.x * blockDim.x + threadIdx.x;
    int tot = KD*Cc + KD;
    if (idx < KD*Cc) d_sums[idx] = 0.f;
    else if (idx < tot) d_counts[idx - KD*Cc] = 0.f;
}

__global__ void k_zero_best() {
    int idx = blockIdx.x * blockDim.x + threadIdx.x;
    d_best[idx] = 0ull;
}

__global__ void k_extract_ind() {
    int idx = blockIdx.x * blockDim.x + threadIdx.x;
    d_ind[idx] = KD - 1 - (int)(uint32_t)(d_best[idx] & 0xFFFFFFFFull);
}

__global__ void k_norm_units(const float* __restrict__ uw) {
    int row  = blockIdx.x * 8 + (threadIdx.x >> 5);
    int lane = threadIdx.x & 31;
    const float* r = uw + (size_t)row * Cc;
    float ss = 0.f;
    for (int j = lane; j < Cc; j += 32) { float v = r[j]; ss += v*v; }
    #pragma unroll
    for (int o = 16; o; o >>= 1) ss += __shfl_xor_sync(0xffffffffu, ss, o);
    float inv = 1.0f / fmaxf(sqrtf(ss), EPS_NORM);
    for (int j = lane; j < Cc; j += 32)
        d_mn0h[(size_t)row*Cc + j] = __float2half(r[j]*inv);
}

__global__ void k_convert_gw(const float* __restrict__ gw) {
    int idx = blockIdx.x * 256 + threadIdx.x;
    d_gwh[idx] = __float2half(gw[idx]);
}

// fused: x (B,C,HW) -> xf/xfh (B*HW, C) + row L2-norm -> xn/xnh
__global__ __launch_bounds__(256)
void k_transnorm(const float* __restrict__ x) {
    __shared__ float tile[256][33];
    int b  = blockIdx.y;
    int s0 = blockIdx.x * 32;
    int tid = threadIdx.x;
    int tx = tid & 31, ty = tid >> 5;
    for (int c = ty; c < Cc; c += 8)
        tile[c][tx] = x[((size_t)(b*Cc + c))*HW + s0 + tx];
    __syncthreads();
    int lane = tx, wrp = ty;
    #pragma unroll
    for (int t = 0; t < 4; t++) {
        int p = wrp + t*8;    // pixel within tile
        float vals[8];
        float ss = 0.f;
        #pragma unroll
        for (int j = 0; j < 8; j++) {
            float v = tile[lane + j*32][p];
            vals[j] = v;
            ss += v*v;
        }
        #pragma unroll
        for (int o = 16; o; o >>= 1) ss += __shfl_xor_sync(0xffffffffu, ss, o);
        float inv = 1.0f / fmaxf(sqrtf(ss), EPS_NORM);
        size_t row = (size_t)b*HW + s0 + p;
        #pragma unroll
        for (int j = 0; j < 8; j++) {
            int c = lane + j*32;
            float v = vals[j];
            float vn = v * inv;
            d_xf [row*Cc + c] = v;
            d_xfh[row*Cc + c] = __float2half(v);
            d_xn [row*Cc + c] = vn;
            d_xnh[row*Cc + c] = __float2half(vn);
        }
    }
}

// KVfull[512,256] = kk^T (512x1024) @ mnew (1024x256) — small, fp32
__global__ __launch_bounds__(256)
void k_gemm_kv()
{
    __shared__ float As[16][68];
    __shared__ float Bs[16][68];
    int tid = threadIdx.x;
    int tx = tid & 15, ty = tid >> 4;
    int rowBase = blockIdx.y * 64, colBase = blockIdx.x * 64;
    float acc[4][4] = {};
    for (int k0 = 0; k0 < KD; k0 += 16) {
        #pragma unroll
        for (int e = 0; e < 4; e++) {
            int t = tid + e*256;
            int kk = t >> 6, r = t & 63;
            As[kk][r] = d_kk[(size_t)(k0 + kk)*(2*Cc) + rowBase + r];
        }
        #pragma unroll
        for (int e = 0; e < 4; e++) {
            int t = tid + e*256;
            int kk = t >> 6, c = t & 63;
            Bs[kk][c] = d_mnew[(size_t)(k0 + kk)*Cc + colBase + c];
        }
        __syncthreads();
        #pragma unroll
        for (int kk = 0; kk < 16; kk++) {
            float a[4], bv[4];
            #pragma unroll
            for (int i = 0; i < 4; i++) a[i]  = As[kk][ty*4 + i];
            #pragma unroll
            for (int j = 0; j < 4; j++) bv[j] = Bs[kk][tx*4 + j];
            #pragma unroll
            for (int i = 0; i < 4; i++)
                #pragma unroll
                for (int j = 0; j < 4; j++) acc[i][j] += a[i]*bv[j];
        }
        __syncthreads();
    }
    #pragma unroll
    for (int i = 0; i < 4; i++) {
        int r = rowBase + ty*4 + i;
        #pragma unroll
        for (int j = 0; j < 4; j++)
            d_kvfull[(size_t)r*Cc + colBase + tx*4 + j] = acc[i][j];
    }
}

// ---------------- EMA path ---------------------------------------------------
__global__ void k_scatter() {
    size_t idx = (size_t)blockIdx.x * blockDim.x + threadIdx.x;
    int i  = (int)(idx >> 8);
    int ch = (int)(idx & 255);
    int code = d_ind[i];
    atomicAdd(&d_sums[(size_t)code*Cc + ch], d_xf[idx]);
    if (ch == 0) atomicAdd(&d_counts[code], 1.0f);
}

__device__ __forceinline__ float fpow(float v, float p) {
    return (v > 0.f) ? exp2f(p * __log2f(v)) : 0.f;
}

__global__ void k_update_codes(const float* __restrict__ uw) {
    __shared__ float red[256];
    int k = blockIdx.x, ch = threadIdx.x;
    float cnt = d_counts[k];
    float em  = d_sums[(size_t)k*Cc + ch] / (cnt + EPS_Z);
    float mv  = uw[(size_t)k*Cc + ch]*RATE + em*(1.0f - RATE);
    d_mnew[(size_t)k*Cc + ch] = mv;
    red[ch] = mv*mv; __syncthreads();
    for (int o = 128; o; o >>= 1) {
        if (ch < o) red[ch] += red[ch+o];
        __syncthreads();
    }
    float inv = 1.0f / fmaxf(sqrtf(red[0]), EPS_NORM);
    float mnv = mv*inv;
    float pv  = d_p[ch];
    d_kk[(size_t)k*(2*Cc) + ch]      = fpow(mnv, pv);
    d_kk[(size_t)k*(2*Cc) + Cc + ch] = fpow(-mnv, pv);
}

__global__ void k_kmean() {
    int col = blockIdx.x * 256 + threadIdx.x;   // 0..511
    float s = 0.f;
    for (int r = 0; r < KD; r++) s += d_kk[(size_t)r*(2*Cc) + col];
    d_kmean[col] = s * (1.0f / KD);
}

// BmatTh[j][r] = kvfull[rr][j]  (fp16, NO 1/N factor), rr = (j<128) ? r : r^256
__global__ void k_bmatT() {
    int idx = blockIdx.x * 256 + threadIdx.x;   // 512*256 total
    int r = idx >> 8, j = idx & 255;
    int rr = (j < Cc/2) ? r : (r ^ Cc);
    d_BmatTh[(size_t)j*(2*Cc) + r] = __float2half(d_kvfull[(size_t)rr*Cc + j]);
}

// ---------------- fused power features + z (one warp per row) ----------------
__global__ void k_powz() {
    int row  = blockIdx.x * 8 + (threadIdx.x >> 5);
    int lane = threadIdx.x & 31;
    const float* xr = d_xn + (size_t)row * Cc;
    __half* qr = d_qcat + (size_t)row * (2*Cc);
    float s1 = 0.f, s2 = 0.f;
    #pragma unroll
    for (int t = 0; t < 8; t++) {
        int c = lane + t*32;
        float v  = xr[c];
        float pv = d_p[c];
        float qp = fpow(v, pv);
        float qn = fpow(-v, pv);
        qr[c]      = __float2half(qp);
        qr[Cc + c] = __float2half(qn);
        float k1 = d_kmean[c], k2 = d_kmean[Cc + c];
        s1 += qp*k1 + qn*k2;
        s2 += qn*k1 + qp*k2;
    }
    #pragma unroll
    for (int o = 16; o; o >>= 1) {
        s1 += __shfl_xor_sync(0xffffffffu, s1, o);
        s2 += __shfl_xor_sync(0xffffffffu, s2, o);
    }
    if (lane == 0) {
        d_z [row] = 1.0f / (s1 + EPS_Z);
        d_z2[row] = 1.0f / (s2 + EPS_Z);
    }
}

// ---------------- fused depthwise conv + gate + transpose-out ----------------
__global__ void k_convout(const float* __restrict__ wgt, const float* __restrict__ bias,
                          float* __restrict__ out) {
    __shared__ float tile[32][33];
    int b  = blockIdx.z;
    int s0 = blockIdx.x * 32, c0 = blockIdx.y * 32;
    int tx = threadIdx.x, ty = threadIdx.y;
    int ch = c0 + tx;
    float w[9];
    #pragma unroll
    for (int k = 0; k < 9; k++) w[k] = wgt[ch*9 + k];
    float bs = bias[ch];
    #pragma unroll
    for (int pi = ty; pi < 32; pi += 8) {
        int s = s0 + pi;
        int h = s >> 6, wc = s & 63;
        size_t i = (size_t)b*HW + s;
        float center = d_xo[i*Cc + ch];
        float acc = bs;
        #pragma unroll
        for (int kh = 0; kh < 3; kh++) {
            int hh = h + kh - 1;
            if (hh < 0 || hh >= Hh) continue;
            #pragma unroll
            for (int kw = 0; kw < 3; kw++) {
                int ww2 = wc + kw - 1;
                if (ww2 < 0 || ww2 >= Ww) continue;
                acc += w[kh*3 + kw] * d_xo[(i + (kh-1)*Ww + (kw-1))*Cc + ch];
            }
        }
        tile[pi][tx] = (center + acc) * d_g[i*Cc + ch];
    }
    __syncthreads();
    #pragma unroll
    for (int r = ty; r < 32; r += 8)
        out[((size_t)(b*Cc + c0 + r))*HW + s0 + tx] = tile[tx][r];
}

// ---------------- launch -----------------------------------------------------
extern "C" void kernel_launch(void* const* d_in, const int* in_sizes, int n_in,
                              void* d_out, int out_size)
{
    const float* x       = (const float*)d_in[0];
    const float* units_w = (const float*)d_in[1];
    const float* power   = (const float*)d_in[2];
    const float* g_w     = (const float*)d_in[3];
    const float* g_b     = (const float*)d_in[4];
    const float* dwc_w   = (const float*)d_in[5];
    const float* dwc_b   = (const float*)d_in[6];

    float* out   = (float*)d_out;                  // (B,C,H,W)
    float* score = (float*)d_out + OUT_ELEMS;      // (N, K)

    // device addresses of scratch globals
    void *p_xfh, *p_xnh, *p_g, *p_xo, *p_qcat, *p_mn0h, *p_gwh, *p_bmatTh;
    cudaGetSymbolAddress(&p_xfh,    d_xfh);
    cudaGetSymbolAddress(&p_xnh,    d_xnh);
    cudaGetSymbolAddress(&p_g,      d_g);
    cudaGetSymbolAddress(&p_xo,     d_xo);
    cudaGetSymbolAddress(&p_qcat,   d_qcat);
    cudaGetSymbolAddress(&p_mn0h,   d_mn0h);
    cudaGetSymbolAddress(&p_gwh,    d_gwh);
    cudaGetSymbolAddress(&p_bmatTh, d_BmatTh);

    k_prep_p<<<1, Cc>>>(power);
    k_zero<<<(KD*Cc + KD + 255)/256, 256>>>();
    k_zero_best<<<Nn/256, 256>>>();
    k_norm_units<<<KD/8, 256>>>(units_w);
    k_convert_gw<<<(Cc*Cc)/256, 256>>>(g_w);

    k_transnorm<<<dim3(HW/32, Bb), 256>>>(x);

    // g = xf @ g_w^T + g_b   (fp16 mma, cp.async)
    k_mma_fp16<1><<<dim3(Cc/128, Nn/128), 256>>>(
        (const __half*)p_xfh, (const __half*)p_gwh, (float*)p_g, g_b, Cc, Cc, 1.f);
    // score = xn @ mn0^T     (fp16 mma, fused argmax)
    k_mma_fp16<0><<<dim3(KD/128, Nn/128), 256>>>(
        (const __half*)p_xnh, (const __half*)p_mn0h, score, nullptr, KD, Cc, 1.f);
    k_extract_ind<<<Nn/256, 256>>>();

    k_scatter<<<(unsigned)((Nn*(size_t)Cc)/256), 256>>>();
    k_update_codes<<<KD, Cc>>>(units_w);
    k_kmean<<<2, 256>>>();
    k_gemm_kv<<<dim3(Cc/64, (2*Cc)/64), 256>>>();
    k_bmatT<<<(2*Cc*Cc)/256, 256>>>();

    k_powz<<<Nn/8, 256>>>();
    // xo = qcat @ BmatTh^T * z/N   (fp16 mma)
    k_mma_fp16<2><<<dim3(Cc/128, Nn/128), 256>>>(
        (const __half*)p_qcat, (const __half*)p_bmatTh, (float*)p_xo, nullptr, Cc, 2*Cc, 1.0f/(float)Nn);

    dim3 tb(32, 8);
    k_convout<<<dim3(HW/32, Cc/32, Bb), tb>>>(dwc_w, dwc_b, out);
}

// round 9
// speedup vs baseline: 3.9822x; 1.1435x over previous
#include <cuda_runtime.h>
#include <cuda_fp16.h>
#include <cstdint>
#include <math.h>

// Problem constants (fixed shapes for this dataset)
#define Bb   8
#define Cc   256
#define Hh   64
#define Ww   64
#define HW   (Hh*Ww)          // 4096
#define Nn   (Bb*HW)          // 32768
#define KD   1024
#define OUT_ELEMS ((size_t)Bb*Cc*HW)   // 8388608

#define EPS_NORM 1e-12f
#define EPS_Z    1e-6f
#define RATE     0.999f

// ---------------- scratch (device globals; no allocation allowed) -----------
__device__ __half d_xfh [(size_t)Nn*Cc];
__device__ __half d_xnh [(size_t)Nn*Cc];
__device__ float  d_g   [(size_t)Nn*Cc];
__device__ float  d_xo  [(size_t)Nn*Cc];
__device__ __half d_qcat[(size_t)Nn*2*Cc];
__device__ __half d_mn0h[(size_t)KD*Cc];
__device__ __half d_gwh [(size_t)Cc*Cc];
__device__ float  d_mnew[(size_t)KD*Cc];
__device__ float  d_kk  [(size_t)KD*2*Cc];
__device__ int    d_cnt [KD];
__device__ int    d_off [KD];
__device__ int    d_cur [KD];
__device__ int    d_rowlist[Nn];
__device__ unsigned long long d_best[Nn];
__device__ float  d_p   [Cc];
__device__ float  d_kmean[2*Cc];
__device__ float  d_kvfull[(size_t)2*Cc*Cc];  // 512 x 256
__device__ __half d_BmatTh[(size_t)Cc*2*Cc];  // 256 x 512 (transposed, NO 1/N)
__device__ float  d_z [Nn];
__device__ float  d_z2[Nn];

// ---------------- helpers -----------------------------------------------------
__device__ __forceinline__ void cp_async16(void* smem_dst, const void* gsrc) {
    uint32_t s = (uint32_t)__cvta_generic_to_shared(smem_dst);
    asm volatile("cp.async.cg.shared.global [%0], [%1], 16;" :: "r"(s), "l"(gsrc));
}
#define CP_COMMIT() asm volatile("cp.async.commit_group;" ::: "memory")
#define CP_WAIT(n)  asm volatile("cp.async.wait_group %0;" :: "n"(n) : "memory")

// pow(|v|, p) with sign split: one LG2 + one EX2 for both branches
__device__ __forceinline__ void pow_pair(float v, float p, float& qp, float& qn) {
    float e = exp2f(p * __log2f(fabsf(v)));   // v==0 -> log2=-inf -> e=0
    qp = (v > 0.f) ? e : 0.f;
    qn = (v < 0.f) ? e : 0.f;
}

// ---------------- fp16 mma.sync NT GEMM (cp.async double-buffered) ----------
// C[M,N2] = A[M,Kd] @ B[N2,Kd]^T  (fp16 gmem operands, fp32 accumulate)
// MODE 0: score (+fused argmax atomics)  MODE 1: + bias[col]
// MODE 2: * (col<128 ? d_z[row] : d_z2[row]) * escale
#define HSTRIDE 40   // halves per smem row (80B, 16B-aligned)

template<int MODE>
__global__ __launch_bounds__(256)
void k_mma_fp16(const __half* __restrict__ A, const __half* __restrict__ B,
                float* __restrict__ Cptr, const float* __restrict__ bias,
                int N2, int Kd, float escale)
{
    __shared__ __half As[2][128*HSTRIDE];
    __shared__ __half Bs[2][128*HSTRIDE];
    int tid  = threadIdx.x;
    int lane = tid & 31, wid = tid >> 5;
    int wm = wid >> 2, wn = wid & 3;       // 2 x 4 warp grid
    int gID = lane >> 2, qd = lane & 3;    // mma fragment coords
    const int rowBase = blockIdx.y * 128;
    const int colBase = blockIdx.x * 128;
    const __half* Ab = A + (size_t)rowBase * Kd;
    const __half* Bb2 = B + (size_t)colBase * Kd;

    float acc[4][4][4];
    #pragma unroll
    for (int i = 0; i < 4; i++)
        #pragma unroll
        for (int j = 0; j < 4; j++)
            #pragma unroll
            for (int t = 0; t < 4; t++) acc[i][j][t] = 0.f;

    const int nKT = Kd >> 5;

    #pragma unroll
    for (int e = 0; e < 2; e++) {
        int idx = tid + e*256;
        int r = idx >> 2, q = idx & 3;
        cp_async16(&As[0][r*HSTRIDE + q*8], Ab + (size_t)r*Kd + q*8);
        cp_async16(&Bs[0][r*HSTRIDE + q*8], Bb2 + (size_t)r*Kd + q*8);
    }
    CP_COMMIT();

    for (int kt = 0; kt < nKT; kt++) {
        int st = kt & 1;
        if (kt + 1 < nKT) {
            int ns = (kt + 1) & 1;
            int koff = (kt + 1) * 32;
            #pragma unroll
            for (int e = 0; e < 2; e++) {
                int idx = tid + e*256;
                int r = idx >> 2, q = idx & 3;
                cp_async16(&As[ns][r*HSTRIDE + q*8], Ab + (size_t)r*Kd + koff + q*8);
                cp_async16(&Bs[ns][r*HSTRIDE + q*8], Bb2 + (size_t)r*Kd + koff + q*8);
            }
            CP_COMMIT();
            CP_WAIT(1);
        } else {
            CP_WAIT(0);
        }
        __syncthreads();

        const __half* Acur = As[st];
        const __half* Bcur = Bs[st];
        #pragma unroll
        for (int ks = 0; ks < 2; ks++) {
            int kb = ks * 16;
            uint32_t bf[4][2];
            #pragma unroll
            for (int j = 0; j < 4; j++) {
                int n0 = wn*32 + j*8 + gID;
                bf[j][0] = *(const uint32_t*)(Bcur + n0*HSTRIDE + kb + 2*qd);
                bf[j][1] = *(const uint32_t*)(Bcur + n0*HSTRIDE + kb + 8 + 2*qd);
            }
            #pragma unroll
            for (int i = 0; i < 4; i++) {
                int m0 = wm*64 + i*16;
                uint32_t a0 = *(const uint32_t*)(Acur + (m0 + gID    )*HSTRIDE + kb + 2*qd);
                uint32_t a1 = *(const uint32_t*)(Acur + (m0 + 8 + gID)*HSTRIDE + kb + 2*qd);
                uint32_t a2 = *(const uint32_t*)(Acur + (m0 + gID    )*HSTRIDE + kb + 8 + 2*qd);
                uint32_t a3 = *(const uint32_t*)(Acur + (m0 + 8 + gID)*HSTRIDE + kb + 8 + 2*qd);
                #pragma unroll
                for (int j = 0; j < 4; j++) {
                    asm volatile(
                        "mma.sync.aligned.m16n8k16.row.col.f32.f16.f16.f32 "
                        "{%0,%1,%2,%3}, {%4,%5,%6,%7}, {%8,%9}, {%0,%1,%2,%3};"
                        : "+f"(acc[i][j][0]), "+f"(acc[i][j][1]),
                          "+f"(acc[i][j][2]), "+f"(acc[i][j][3])
                        : "r"(a0), "r"(a1), "r"(a2), "r"(a3),
                          "r"(bf[j][0]), "r"(bf[j][1]));
                }
            }
        }
        __syncthreads();
    }

    // ---- epilogue ----
    #pragma unroll
    for (int i = 0; i < 4; i++) {
        int r0 = rowBase + wm*64 + i*16 + gID;
        int r1 = r0 + 8;
        float s0 = 1.f, s1 = 1.f;
        if (MODE == 2) {
            bool firstHalf = (colBase < Cc/2);
            s0 = (firstHalf ? d_z[r0] : d_z2[r0]) * escale;
            s1 = (firstHalf ? d_z[r1] : d_z2[r1]) * escale;
        }
        unsigned long long best0 = 0ull, best1 = 0ull;
        #pragma unroll
        for (int j = 0; j < 4; j++) {
            int c0 = colBase + wn*32 + j*8 + 2*qd;
            float v00 = acc[i][j][0], v01 = acc[i][j][1];
            float v10 = acc[i][j][2], v11 = acc[i][j][3];
            if (MODE == 1) {
                float b0 = bias[c0], b1 = bias[c0+1];
                v00 += b0; v01 += b1; v10 += b0; v11 += b1;
            } else if (MODE == 2) {
                v00 *= s0; v01 *= s0; v10 *= s1; v11 *= s1;
            }
            *(float2*)(Cptr + (size_t)r0*N2 + c0) = make_float2(v00, v01);
            *(float2*)(Cptr + (size_t)r1*N2 + c0) = make_float2(v10, v11);
            if (MODE == 0) {
                uint32_t k00 = __float_as_uint(v00); k00 ^= (k00 & 0x80000000u) ? 0xFFFFFFFFu : 0x80000000u;
                uint32_t k01 = __float_as_uint(v01); k01 ^= (k01 & 0x80000000u) ? 0xFFFFFFFFu : 0x80000000u;
                uint32_t k10 = __float_as_uint(v10); k10 ^= (k10 & 0x80000000u) ? 0xFFFFFFFFu : 0x80000000u;
                uint32_t k11 = __float_as_uint(v11); k11 ^= (k11 & 0x80000000u) ? 0xFFFFFFFFu : 0x80000000u;
                unsigned long long p00 = ((unsigned long long)k00 << 32) | (uint32_t)(KD-1-c0);
                unsigned long long p01 = ((unsigned long long)k01 << 32) | (uint32_t)(KD-2-c0);
                unsigned long long p10 = ((unsigned long long)k10 << 32) | (uint32_t)(KD-1-c0);
                unsigned long long p11 = ((unsigned long long)k11 << 32) | (uint32_t)(KD-2-c0);
                if (p01 > p00) p00 = p01;
                if (p11 > p10) p10 = p11;
                if (p00 > best0) best0 = p00;
                if (p10 > best1) best1 = p10;
            }
        }
        if (MODE == 0) {
            #pragma unroll
            for (int o = 1; o <= 2; o <<= 1) {
                unsigned long long t0 = __shfl_xor_sync(0xffffffffu, best0, o);
                unsigned long long t1 = __shfl_xor_sync(0xffffffffu, best1, o);
                if (t0 > best0) best0 = t0;
                if (t1 > best1) best1 = t1;
            }
            if (qd == 0) {
                atomicMax(&d_best[r0], best0);
                atomicMax(&d_best[r1], best1);
            }
        }
    }
}

// ---------------- merged init: gwh convert + p + zero best/cnt/kmean --------
__global__ void k_init(const float* __restrict__ power, const float* __restrict__ gw) {
    int idx = blockIdx.x * 256 + threadIdx.x;      // 65536 threads
    d_gwh[idx] = __float2half(gw[idx]);            // Cc*Cc = 65536 exactly
    if (idx < Nn) d_best[idx] = 0ull;
    if (idx < KD) d_cnt[idx] = 0;
    if (idx < 2*Cc) d_kmean[idx] = 0.f;
    if (idx < Cc) {
        float pw = power[idx];
        d_p[idx] = 1.0f + 4.0f / (1.0f + __expf(-pw));
    }
}

// one block per codebook row
__global__ void k_norm_units(const float* __restrict__ uw) {
    __shared__ float red[256];
    int k = blockIdx.x, ch = threadIdx.x;
    float v = uw[(size_t)k*Cc + ch];
    red[ch] = v*v; __syncthreads();
    for (int o = 128; o; o >>= 1) {
        if (ch < o) red[ch] += red[ch+o];
        __syncthreads();
    }
    float inv = 1.0f / fmaxf(sqrtf(red[0]), EPS_NORM);
    d_mn0h[(size_t)k*Cc + ch] = __float2half(v*inv);
}

// fused: x (B,C,HW) -> xfh/xnh (fp16) + power features qcat (fp16)
__global__ __launch_bounds__(256)
void k_transnorm(const float* __restrict__ x) {
    __shared__ float tile[256][33];
    int b  = blockIdx.y;
    int s0 = blockIdx.x * 32;
    int tid = threadIdx.x;
    int tx = tid & 31, ty = tid >> 5;
    for (int c = ty; c < Cc; c += 8)
        tile[c][tx] = x[((size_t)(b*Cc + c))*HW + s0 + tx];
    __syncthreads();
    int lane = tx, wrp = ty;
    #pragma unroll
    for (int t = 0; t < 4; t++) {
        int p = wrp + t*8;
        float vals[8];
        float ss = 0.f;
        #pragma unroll
        for (int j = 0; j < 8; j++) {
            float v = tile[lane + j*32][p];
            vals[j] = v;
            ss += v*v;
        }
        #pragma unroll
        for (int o = 16; o; o >>= 1) ss += __shfl_xor_sync(0xffffffffu, ss, o);
        float inv = 1.0f / fmaxf(sqrtf(ss), EPS_NORM);
        size_t row = (size_t)b*HW + s0 + p;
        #pragma unroll
        for (int j = 0; j < 8; j++) {
            int c = lane + j*32;
            float v  = vals[j];
            float vn = v * inv;
            d_xfh[row*Cc + c] = __float2half(v);
            d_xnh[row*Cc + c] = __float2half(vn);
            float qp, qn;
            pow_pair(vn, d_p[c], qp, qn);
            d_qcat[row*(2*Cc) + c]      = __float2half(qp);
            d_qcat[row*(2*Cc) + Cc + c] = __float2half(qn);
        }
    }
}

// ---------------- counting-sort EMA path -------------------------------------
__device__ __forceinline__ int best_code(unsigned long long b) {
    return KD - 1 - (int)(uint32_t)(b & 0xFFFFFFFFull);
}

__global__ void k_count() {
    int idx = blockIdx.x * 256 + threadIdx.x;
    atomicAdd(&d_cnt[best_code(d_best[idx])], 1);
}

__global__ void k_scan() {   // 1 block, 1024 threads: exclusive scan
    __shared__ int s[1024];
    int t = threadIdx.x;
    int v = d_cnt[t];
    s[t] = v; __syncthreads();
    for (int o = 1; o < 1024; o <<= 1) {
        int add = (t >= o) ? s[t-o] : 0;
        __syncthreads();
        s[t] += add;
        __syncthreads();
    }
    d_off[t] = s[t] - v;
    d_cur[t] = s[t] - v;
}

__global__ void k_fill() {
    int idx = blockIdx.x * 256 + threadIdx.x;
    int code = best_code(d_best[idx]);
    int pos = atomicAdd(&d_cur[code], 1);
    d_rowlist[pos] = idx;
}

__global__ void k_update_codes(const float* __restrict__ uw) {
    __shared__ float red[256];
    int k = blockIdx.x, ch = threadIdx.x;
    int cnt = d_cnt[k], off = d_off[k];
    float sum = 0.f;
    for (int t = 0; t < cnt; t++) {
        int row = d_rowlist[off + t];
        sum += __half2float(d_xfh[(size_t)row*Cc + ch]);
    }
    float em = sum / ((float)cnt + EPS_Z);
    float mv = uw[(size_t)k*Cc + ch]*RATE + em*(1.0f - RATE);
    d_mnew[(size_t)k*Cc + ch] = mv;
    red[ch] = mv*mv; __syncthreads();
    for (int o = 128; o; o >>= 1) {
        if (ch < o) red[ch] += red[ch+o];
        __syncthreads();
    }
    float inv = 1.0f / fmaxf(sqrtf(red[0]), EPS_NORM);
    float mnv = mv*inv;
    float qp, qn;
    pow_pair(mnv, d_p[ch], qp, qn);
    d_kk[(size_t)k*(2*Cc) + ch]      = qp;
    d_kk[(size_t)k*(2*Cc) + Cc + ch] = qn;
}

__global__ void k_kmean() {  // grid (2, 8), 256 threads
    int col = blockIdx.x * 256 + threadIdx.x;
    int r0 = blockIdx.y * 128;
    float s = 0.f;
    for (int r = r0; r < r0 + 128; r++) s += d_kk[(size_t)r*(2*Cc) + col];
    atomicAdd(&d_kmean[col], s * (1.0f / KD));
}

// KVfull[512,256] = kk^T (512x1024) @ mnew (1024x256) — small, fp32
__global__ __launch_bounds__(256)
void k_gemm_kv()
{
    __shared__ float As[16][68];
    __shared__ float Bs[16][68];
    int tid = threadIdx.x;
    int tx = tid & 15, ty = tid >> 4;
    int rowBase = blockIdx.y * 64, colBase = blockIdx.x * 64;
    float acc[4][4] = {};
    for (int k0 = 0; k0 < KD; k0 += 16) {
        #pragma unroll
        for (int e = 0; e < 4; e++) {
            int t = tid + e*256;
            int kk = t >> 6, r = t & 63;
            As[kk][r] = d_kk[(size_t)(k0 + kk)*(2*Cc) + rowBase + r];
        }
        #pragma unroll
        for (int e = 0; e < 4; e++) {
            int t = tid + e*256;
            int kk = t >> 6, c = t & 63;
            Bs[kk][c] = d_mnew[(size_t)(k0 + kk)*Cc + colBase + c];
        }
        __syncthreads();
        #pragma unroll
        for (int kk = 0; kk < 16; kk++) {
            float a[4], bv[4];
            #pragma unroll
            for (int i = 0; i < 4; i++) a[i]  = As[kk][ty*4 + i];
            #pragma unroll
            for (int j = 0; j < 4; j++) bv[j] = Bs[kk][tx*4 + j];
            #pragma unroll
            for (int i = 0; i < 4; i++)
                #pragma unroll
                for (int j = 0; j < 4; j++) acc[i][j] += a[i]*bv[j];
        }
        __syncthreads();
    }
    #pragma unroll
    for (int i = 0; i < 4; i++) {
        int r = rowBase + ty*4 + i;
        #pragma unroll
        for (int j = 0; j < 4; j++)
            d_kvfull[(size_t)r*Cc + colBase + tx*4 + j] = acc[i][j];
    }
}

// BmatTh[j][r] = kvfull[rr][j]  (fp16, NO 1/N factor), rr = (j<128) ? r : r^256
__global__ void k_bmatT() {
    int idx = blockIdx.x * 256 + threadIdx.x;   // 512*256 total
    int r = idx >> 8, j = idx & 255;
    int rr = (j < Cc/2) ? r : (r ^ Cc);
    d_BmatTh[(size_t)j*(2*Cc) + r] = __float2half(d_kvfull[(size_t)rr*Cc + j]);
}

// ---------------- z from fp16 qcat (one warp per row) -------------------------
__global__ void k_zrow() {
    int row  = blockIdx.x * 8 + (threadIdx.x >> 5);
    int lane = threadIdx.x & 31;
    const __half2* q = (const __half2*)(d_qcat + (size_t)row * (2*Cc));
    float s1 = 0.f, s2 = 0.f;
    #pragma unroll
    for (int t = 0; t < 8; t++) {
        int c2 = lane + t*32;           // half2 index 0..255
        float2 qf = __half22float2(q[c2]);
        int c = 2*c2;
        float k1a = d_kmean[c],         k1b = d_kmean[c+1];
        float k2a = d_kmean[c ^ (2*Cc/2)], k2b = d_kmean[(c+1) ^ (2*Cc/2)];
        s1 += qf.x*k1a + qf.y*k1b;
        s2 += qf.x*k2a + qf.y*k2b;
    }
    #pragma unroll
    for (int o = 16; o; o >>= 1) {
        s1 += __shfl_xor_sync(0xffffffffu, s1, o);
        s2 += __shfl_xor_sync(0xffffffffu, s2, o);
    }
    if (lane == 0) {
        d_z [row] = 1.0f / (s1 + EPS_Z);
        d_z2[row] = 1.0f / (s2 + EPS_Z);
    }
}

// ---------------- fused depthwise conv + gate + transpose-out ----------------
__global__ void k_convout(const float* __restrict__ wgt, const float* __restrict__ bias,
                          float* __restrict__ out) {
    __shared__ float tile[32][33];
    int b  = blockIdx.z;
    int s0 = blockIdx.x * 32, c0 = blockIdx.y * 32;
    int tx = threadIdx.x, ty = threadIdx.y;
    int ch = c0 + tx;
    float w[9];
    #pragma unroll
    for (int k = 0; k < 9; k++) w[k] = wgt[ch*9 + k];
    float bs = bias[ch];
    #pragma unroll
    for (int pi = ty; pi < 32; pi += 8) {
        int s = s0 + pi;
        int h = s >> 6, wc = s & 63;
        size_t i = (size_t)b*HW + s;
        float center = d_xo[i*Cc + ch];
        float acc = bs;
        #pragma unroll
        for (int kh = 0; kh < 3; kh++) {
            int hh = h + kh - 1;
            if (hh < 0 || hh >= Hh) continue;
            #pragma unroll
            for (int kw = 0; kw < 3; kw++) {
                int ww2 = wc + kw - 1;
                if (ww2 < 0 || ww2 >= Ww) continue;
                acc += w[kh*3 + kw] * d_xo[(i + (kh-1)*Ww + (kw-1))*Cc + ch];
            }
        }
        tile[pi][tx] = (center + acc) * d_g[i*Cc + ch];
    }
    __syncthreads();
    #pragma unroll
    for (int r = ty; r < 32; r += 8)
        out[((size_t)(b*Cc + c0 + r))*HW + s0 + tx] = tile[tx][r];
}

// ---------------- launch -----------------------------------------------------
extern "C" void kernel_launch(void* const* d_in, const int* in_sizes, int n_in,
                              void* d_out, int out_size)
{
    const float* x       = (const float*)d_in[0];
    const float* units_w = (const float*)d_in[1];
    const float* power   = (const float*)d_in[2];
    const float* g_w     = (const float*)d_in[3];
    const float* g_b     = (const float*)d_in[4];
    const float* dwc_w   = (const float*)d_in[5];
    const float* dwc_b   = (const float*)d_in[6];

    float* out   = (float*)d_out;                  // (B,C,H,W)
    float* score = (float*)d_out + OUT_ELEMS;      // (N, K)

    void *p_xfh, *p_xnh, *p_g, *p_xo, *p_qcat, *p_mn0h, *p_gwh, *p_bmatTh;
    cudaGetSymbolAddress(&p_xfh,    d_xfh);
    cudaGetSymbolAddress(&p_xnh,    d_xnh);
    cudaGetSymbolAddress(&p_g,      d_g);
    cudaGetSymbolAddress(&p_xo,     d_xo);
    cudaGetSymbolAddress(&p_qcat,   d_qcat);
    cudaGetSymbolAddress(&p_mn0h,   d_mn0h);
    cudaGetSymbolAddress(&p_gwh,    d_gwh);
    cudaGetSymbolAddress(&p_bmatTh, d_BmatTh);

    k_init<<<(Cc*Cc)/256, 256>>>(power, g_w);
    k_norm_units<<<KD, 256>>>(units_w);
    k_transnorm<<<dim3(HW/32, Bb), 256>>>(x);

    // g = xf @ g_w^T + g_b   (fp16 mma)
    k_mma_fp16<1><<<dim3(Cc/128, Nn/128), 256>>>(
        (const __half*)p_xfh, (const __half*)p_gwh, (float*)p_g, g_b, Cc, Cc, 1.f);
    // score = xn @ mn0^T     (fp16 mma, fused argmax)
    k_mma_fp16<0><<<dim3(KD/128, Nn/128), 256>>>(
        (const __half*)p_xnh, (const __half*)p_mn0h, score, nullptr, KD, Cc, 1.f);

    k_count<<<Nn/256, 256>>>();
    k_scan<<<1, 1024>>>();
    k_fill<<<Nn/256, 256>>>();
    k_update_codes<<<KD, 256>>>(units_w);
    k_kmean<<<dim3(2, 8), 256>>>();
    k_gemm_kv<<<dim3(Cc/64, (2*Cc)/64), 256>>>();
    k_bmatT<<<(2*Cc*Cc)/256, 256>>>();

    k_zrow<<<Nn/8, 256>>>();
    // xo = qcat @ BmatTh^T * z/N   (fp16 mma)
    k_mma_fp16<2><<<dim3(Cc/128, Nn/128), 256>>>(
        (const __half*)p_qcat, (const __half*)p_bmatTh, (float*)p_xo, nullptr, Cc, 2*Cc, 1.0f/(float)Nn);

    dim3 tb(32, 8);
    k_convout<<<dim3(HW/32, Cc/32, Bb), tb>>>(dwc_w, dwc_b, out);
}

// round 10
// speedup vs baseline: 4.1731x; 1.0479x over previous
#include <cuda_runtime.h>
#include <cuda_fp16.h>
#include <cstdint>
#include <math.h>

// Problem constants (fixed shapes for this dataset)
#define Bb   8
#define Cc   256
#define Hh   64
#define Ww   64
#define HW   (Hh*Ww)          // 4096
#define Nn   (Bb*HW)          // 32768
#define KD   1024
#define OUT_ELEMS ((size_t)Bb*Cc*HW)   // 8388608

#define EPS_NORM 1e-12f
#define EPS_Z    1e-6f
#define RATE     0.999f

// ---------------- scratch (device globals; no allocation allowed) -----------
__device__ __half d_xfh [(size_t)Nn*Cc];
__device__ float  d_rinv[Nn];
__device__ float  d_g   [(size_t)Nn*Cc];
__device__ float  d_xo  [(size_t)Nn*Cc];
__device__ __half d_qcat[(size_t)Nn*2*Cc];
__device__ __half d_bigBh[(size_t)(Cc+KD)*Cc];  // rows 0-255: g_w; 256-1279: mn0
__device__ float  d_mnew[(size_t)KD*Cc];
__device__ float  d_kk  [(size_t)KD*2*Cc];
__device__ int    d_cnt [KD];
__device__ int    d_off [KD];
__device__ int    d_cur [KD];
__device__ int    d_rowlist[Nn];
__device__ unsigned long long d_best[Nn];
__device__ float  d_p   [Cc];
__device__ float  d_kmean[2*Cc];
__device__ float  d_kvfull[(size_t)2*Cc*Cc];  // 512 x 256
__device__ __half d_BmatTh[(size_t)Cc*2*Cc];  // 256 x 512 (transposed, NO 1/N)
__device__ float  d_z [Nn];
__device__ float  d_z2[Nn];

// ---------------- helpers -----------------------------------------------------
__device__ __forceinline__ void cp_async16(void* smem_dst, const void* gsrc) {
    uint32_t s = (uint32_t)__cvta_generic_to_shared(smem_dst);
    asm volatile("cp.async.cg.shared.global [%0], [%1], 16;" :: "r"(s), "l"(gsrc));
}
#define CP_COMMIT() asm volatile("cp.async.commit_group;" ::: "memory")
#define CP_WAIT(n)  asm volatile("cp.async.wait_group %0;" :: "n"(n) : "memory")

__device__ __forceinline__ void ldsm_x4(uint32_t& r0, uint32_t& r1, uint32_t& r2,
                                        uint32_t& r3, const void* p) {
    uint32_t a = (uint32_t)__cvta_generic_to_shared(p);
    asm volatile("ldmatrix.sync.aligned.m8n8.x4.shared.b16 {%0,%1,%2,%3}, [%4];"
        : "=r"(r0), "=r"(r1), "=r"(r2), "=r"(r3) : "r"(a));
}
__device__ __forceinline__ void ldsm_x2(uint32_t& r0, uint32_t& r1, const void* p) {
    uint32_t a = (uint32_t)__cvta_generic_to_shared(p);
    asm volatile("ldmatrix.sync.aligned.m8n8.x2.shared.b16 {%0,%1}, [%2];"
        : "=r"(r0), "=r"(r1) : "r"(a));
}

// pow(|v|, p) with sign split: one LG2 + one EX2 for both branches
__device__ __forceinline__ void pow_pair(float v, float p, float& qp, float& qn) {
    float e = exp2f(p * __log2f(fabsf(v)));   // v==0 -> log2=-inf -> e=0
    qp = (v > 0.f) ? e : 0.f;
    qn = (v < 0.f) ? e : 0.f;
}

// ---------------- fp16 mma.sync NT GEMM (3-stage cp.async, ldmatrix) --------
// MODE 3: merged g+score — C1=d_g (+bias, cols<256), C2=score (*rinv, fused argmax)
// MODE 2: xo — C1=xo, scale by (col<128 ? z : z2) * escale
#define HSTRIDE 40   // halves per smem row (80B, 16B-aligned)
#define STG_SZ  (2*128*HSTRIDE)          // halves per stage (A then B)
#define MMA_SMEM_BYTES (3*STG_SZ*2)      // 61440 B

template<int MODE>
__global__ __launch_bounds__(256)
void k_mma(const __half* __restrict__ A, const __half* __restrict__ B,
           float* __restrict__ C1, float* __restrict__ C2,
           const float* __restrict__ bias, int Kd, float escale)
{
    extern __shared__ __half sh[];
    int tid  = threadIdx.x;
    int lane = tid & 31, wid = tid >> 5;
    int wm = wid >> 2, wn = wid & 3;       // 2 x 4 warp grid
    int gID = lane >> 2, qd = lane & 3;
    const int rowBase = blockIdx.y * 128;
    const int colBase = blockIdx.x * 128;
    const __half* Agm = A + (size_t)rowBase * Kd;
    const __half* Bgm = B + (size_t)colBase * Kd;

    // ldmatrix per-lane row/col offsets (in halves)
    int la_row = lane & 15, la_k8 = (lane >> 4) * 8;          // A x4
    int lb_row = lane & 7,  lb_k8 = ((lane >> 3) & 1) * 8;    // B x2

    float acc[4][4][4];
    #pragma unroll
    for (int i = 0; i < 4; i++)
        #pragma unroll
        for (int j = 0; j < 4; j++)
            #pragma unroll
            for (int t = 0; t < 4; t++) acc[i][j][t] = 0.f;

    const int nKT = Kd >> 5;

    // prologue: stages 0,1
    #pragma unroll
    for (int s = 0; s < 2; s++) {
        __half* As = sh + s*STG_SZ;
        __half* Bs = As + 128*HSTRIDE;
        int koff = s * 32;
        #pragma unroll
        for (int e = 0; e < 2; e++) {
            int idx = tid + e*256;
            int r = idx >> 2, q = idx & 3;
            cp_async16(&As[r*HSTRIDE + q*8], Agm + (size_t)r*Kd + koff + q*8);
            cp_async16(&Bs[r*HSTRIDE + q*8], Bgm + (size_t)r*Kd + koff + q*8);
        }
        CP_COMMIT();
    }

    for (int kt = 0; kt < nKT; kt++) {
        if (kt < nKT - 1) { CP_WAIT(1); } else { CP_WAIT(0); }
        __syncthreads();
        // prefetch stage kt+2 (safe: all threads past kt-1's reads of this buffer)
        if (kt + 2 < nKT) {
            int s = (kt + 2) % 3;
            __half* As = sh + s*STG_SZ;
            __half* Bs = As + 128*HSTRIDE;
            int koff = (kt + 2) * 32;
            #pragma unroll
            for (int e = 0; e < 2; e++) {
                int idx = tid + e*256;
                int r = idx >> 2, q = idx & 3;
                cp_async16(&As[r*HSTRIDE + q*8], Agm + (size_t)r*Kd + koff + q*8);
                cp_async16(&Bs[r*HSTRIDE + q*8], Bgm + (size_t)r*Kd + koff + q*8);
            }
            CP_COMMIT();
        }

        const __half* Acur = sh + (kt % 3)*STG_SZ;
        const __half* Bcur = Acur + 128*HSTRIDE;
        #pragma unroll
        for (int ks = 0; ks < 2; ks++) {
            int kb = ks * 16;
            uint32_t bf[4][2];
            #pragma unroll
            for (int j = 0; j < 4; j++) {
                int n0 = wn*32 + j*8;
                ldsm_x2(bf[j][0], bf[j][1],
                        Bcur + (n0 + lb_row)*HSTRIDE + kb + lb_k8);
            }
            #pragma unroll
            for (int i = 0; i < 4; i++) {
                int m0 = wm*64 + i*16;
                uint32_t a0, a1, a2, a3;
                ldsm_x4(a0, a1, a2, a3,
                        Acur + (m0 + la_row)*HSTRIDE + kb + la_k8);
                #pragma unroll
                for (int j = 0; j < 4; j++) {
                    asm volatile(
                        "mma.sync.aligned.m16n8k16.row.col.f32.f16.f16.f32 "
                        "{%0,%1,%2,%3}, {%4,%5,%6,%7}, {%8,%9}, {%0,%1,%2,%3};"
                        : "+f"(acc[i][j][0]), "+f"(acc[i][j][1]),
                          "+f"(acc[i][j][2]), "+f"(acc[i][j][3])
                        : "r"(a0), "r"(a1), "r"(a2), "r"(a3),
                          "r"(bf[j][0]), "r"(bf[j][1]));
                }
            }
        }
    }

    // ---- epilogue ----
    bool scoreTile = (MODE == 3) && (colBase >= Cc);
    #pragma unroll
    for (int i = 0; i < 4; i++) {
        int r0 = rowBase + wm*64 + i*16 + gID;
        int r1 = r0 + 8;
        float s0 = 1.f, s1 = 1.f;
        if (MODE == 2) {
            bool firstHalf = (colBase < Cc/2);
            s0 = (firstHalf ? d_z[r0] : d_z2[r0]) * escale;
            s1 = (firstHalf ? d_z[r1] : d_z2[r1]) * escale;
        } else if (scoreTile) {
            s0 = d_rinv[r0];
            s1 = d_rinv[r1];
        }
        unsigned long long best0 = 0ull, best1 = 0ull;
        #pragma unroll
        for (int j = 0; j < 4; j++) {
            int c0 = colBase + wn*32 + j*8 + 2*qd;
            float v00 = acc[i][j][0], v01 = acc[i][j][1];
            float v10 = acc[i][j][2], v11 = acc[i][j][3];
            if (MODE == 2) {
                v00 *= s0; v01 *= s0; v10 *= s1; v11 *= s1;
                *(float2*)(C1 + (size_t)r0*Cc + c0) = make_float2(v00, v01);
                *(float2*)(C1 + (size_t)r1*Cc + c0) = make_float2(v10, v11);
            } else if (!scoreTile) {
                float b0 = bias[c0], b1 = bias[c0+1];
                v00 += b0; v01 += b1; v10 += b0; v11 += b1;
                *(float2*)(C1 + (size_t)r0*Cc + c0) = make_float2(v00, v01);
                *(float2*)(C1 + (size_t)r1*Cc + c0) = make_float2(v10, v11);
            } else {
                int cs = c0 - Cc;
                v00 *= s0; v01 *= s0; v10 *= s1; v11 *= s1;
                *(float2*)(C2 + (size_t)r0*KD + cs) = make_float2(v00, v01);
                *(float2*)(C2 + (size_t)r1*KD + cs) = make_float2(v10, v11);
                uint32_t k00 = __float_as_uint(v00); k00 ^= (k00 & 0x80000000u) ? 0xFFFFFFFFu : 0x80000000u;
                uint32_t k01 = __float_as_uint(v01); k01 ^= (k01 & 0x80000000u) ? 0xFFFFFFFFu : 0x80000000u;
                uint32_t k10 = __float_as_uint(v10); k10 ^= (k10 & 0x80000000u) ? 0xFFFFFFFFu : 0x80000000u;
                uint32_t k11 = __float_as_uint(v11); k11 ^= (k11 & 0x80000000u) ? 0xFFFFFFFFu : 0x80000000u;
                unsigned long long p00 = ((unsigned long long)k00 << 32) | (uint32_t)(KD-1-cs);
                unsigned long long p01 = ((unsigned long long)k01 << 32) | (uint32_t)(KD-2-cs);
                unsigned long long p10 = ((unsigned long long)k10 << 32) | (uint32_t)(KD-1-cs);
                unsigned long long p11 = ((unsigned long long)k11 << 32) | (uint32_t)(KD-2-cs);
                if (p01 > p00) p00 = p01;
                if (p11 > p10) p10 = p11;
                if (p00 > best0) best0 = p00;
                if (p10 > best1) best1 = p10;
            }
        }
        if (scoreTile) {
            #pragma unroll
            for (int o = 1; o <= 2; o <<= 1) {
                unsigned long long t0 = __shfl_xor_sync(0xffffffffu, best0, o);
                unsigned long long t1 = __shfl_xor_sync(0xffffffffu, best1, o);
                if (t0 > best0) best0 = t0;
                if (t1 > best1) best1 = t1;
            }
            if (qd == 0) {
                atomicMax(&d_best[r0], best0);
                atomicMax(&d_best[r1], best1);
            }
        }
    }
}

// ---------------- merged init: gw convert into bigB + p + zero best/cnt/kmean
__global__ void k_init(const float* __restrict__ power, const float* __restrict__ gw) {
    int idx = blockIdx.x * 256 + threadIdx.x;      // 65536 threads
    d_bigBh[idx] = __float2half(gw[idx]);          // rows 0-255 of bigB
    if (idx < Nn) d_best[idx] = 0ull;
    if (idx < KD) d_cnt[idx] = 0;
    if (idx < 2*Cc) d_kmean[idx] = 0.f;
    if (idx < Cc) {
        float pw = power[idx];
        d_p[idx] = 1.0f + 4.0f / (1.0f + __expf(-pw));
    }
}

// one block per codebook row -> normalized fp16 into bigB rows 256..1279
__global__ void k_norm_units(const float* __restrict__ uw) {
    __shared__ float red[256];
    int k = blockIdx.x, ch = threadIdx.x;
    float v = uw[(size_t)k*Cc + ch];
    red[ch] = v*v; __syncthreads();
    for (int o = 128; o; o >>= 1) {
        if (ch < o) red[ch] += red[ch+o];
        __syncthreads();
    }
    float inv = 1.0f / fmaxf(sqrtf(red[0]), EPS_NORM);
    d_bigBh[(size_t)(Cc + k)*Cc + ch] = __float2half(v*inv);
}

// fused: x (B,C,HW) -> xfh (fp16) + rinv + power features qcat (fp16)
__global__ __launch_bounds__(256)
void k_transnorm(const float* __restrict__ x) {
    __shared__ float tile[256][33];
    int b  = blockIdx.y;
    int s0 = blockIdx.x * 32;
    int tid = threadIdx.x;
    int tx = tid & 31, ty = tid >> 5;
    for (int c = ty; c < Cc; c += 8)
        tile[c][tx] = x[((size_t)(b*Cc + c))*HW + s0 + tx];
    __syncthreads();
    int lane = tx, wrp = ty;
    #pragma unroll
    for (int t = 0; t < 4; t++) {
        int p = wrp + t*8;
        float vals[8];
        float ss = 0.f;
        #pragma unroll
        for (int j = 0; j < 8; j++) {
            float v = tile[lane + j*32][p];
            vals[j] = v;
            ss += v*v;
        }
        #pragma unroll
        for (int o = 16; o; o >>= 1) ss += __shfl_xor_sync(0xffffffffu, ss, o);
        float inv = 1.0f / fmaxf(sqrtf(ss), EPS_NORM);
        size_t row = (size_t)b*HW + s0 + p;
        if (lane == 0) d_rinv[row] = inv;
        #pragma unroll
        for (int j = 0; j < 8; j++) {
            int c = lane + j*32;
            float v  = vals[j];
            float vn = v * inv;
            d_xfh[row*Cc + c] = __float2half(v);
            float qp, qn;
            pow_pair(vn, d_p[c], qp, qn);
            d_qcat[row*(2*Cc) + c]      = __float2half(qp);
            d_qcat[row*(2*Cc) + Cc + c] = __float2half(qn);
        }
    }
}

// ---------------- counting-sort EMA path -------------------------------------
__device__ __forceinline__ int best_code(unsigned long long b) {
    return KD - 1 - (int)(uint32_t)(b & 0xFFFFFFFFull);
}

__global__ void k_count() {
    int idx = blockIdx.x * 256 + threadIdx.x;
    atomicAdd(&d_cnt[best_code(d_best[idx])], 1);
}

__global__ void k_scan() {   // 1 block, 1024 threads: exclusive scan
    __shared__ int s[1024];
    int t = threadIdx.x;
    int v = d_cnt[t];
    s[t] = v; __syncthreads();
    for (int o = 1; o < 1024; o <<= 1) {
        int add = (t >= o) ? s[t-o] : 0;
        __syncthreads();
        s[t] += add;
        __syncthreads();
    }
    d_off[t] = s[t] - v;
    d_cur[t] = s[t] - v;
}

__global__ void k_fill() {
    int idx = blockIdx.x * 256 + threadIdx.x;
    int code = best_code(d_best[idx]);
    int pos = atomicAdd(&d_cur[code], 1);
    d_rowlist[pos] = idx;
}

__global__ void k_update_codes(const float* __restrict__ uw) {
    __shared__ float red[256];
    int k = blockIdx.x, ch = threadIdx.x;
    int cnt = d_cnt[k], off = d_off[k];
    float sum = 0.f;
    for (int t = 0; t < cnt; t++) {
        int row = d_rowlist[off + t];
        sum += __half2float(d_xfh[(size_t)row*Cc + ch]);
    }
    float em = sum / ((float)cnt + EPS_Z);
    float mv = uw[(size_t)k*Cc + ch]*RATE + em*(1.0f - RATE);
    d_mnew[(size_t)k*Cc + ch] = mv;
    red[ch] = mv*mv; __syncthreads();
    for (int o = 128; o; o >>= 1) {
        if (ch < o) red[ch] += red[ch+o];
        __syncthreads();
    }
    float inv = 1.0f / fmaxf(sqrtf(red[0]), EPS_NORM);
    float mnv = mv*inv;
    float qp, qn;
    pow_pair(mnv, d_p[ch], qp, qn);
    d_kk[(size_t)k*(2*Cc) + ch]      = qp;
    d_kk[(size_t)k*(2*Cc) + Cc + ch] = qn;
}

__global__ void k_kmean() {  // grid (2, 8), 256 threads
    int col = blockIdx.x * 256 + threadIdx.x;
    int r0 = blockIdx.y * 128;
    float s = 0.f;
    for (int r = r0; r < r0 + 128; r++) s += d_kk[(size_t)r*(2*Cc) + col];
    atomicAdd(&d_kmean[col], s * (1.0f / KD));
}

// KVfull[512,256] = kk^T (512x1024) @ mnew (1024x256) — small, fp32
__global__ __launch_bounds__(256)
void k_gemm_kv()
{
    __shared__ float As[16][68];
    __shared__ float Bs[16][68];
    int tid = threadIdx.x;
    int tx = tid & 15, ty = tid >> 4;
    int rowBase = blockIdx.y * 64, colBase = blockIdx.x * 64;
    float acc[4][4] = {};
    for (int k0 = 0; k0 < KD; k0 += 16) {
        #pragma unroll
        for (int e = 0; e < 4; e++) {
            int t = tid + e*256;
            int kk = t >> 6, r = t & 63;
            As[kk][r] = d_kk[(size_t)(k0 + kk)*(2*Cc) + rowBase + r];
        }
        #pragma unroll
        for (int e = 0; e < 4; e++) {
            int t = tid + e*256;
            int kk = t >> 6, c = t & 63;
            Bs[kk][c] = d_mnew[(size_t)(k0 + kk)*Cc + colBase + c];
        }
        __syncthreads();
        #pragma unroll
        for (int kk = 0; kk < 16; kk++) {
            float a[4], bv[4];
            #pragma unroll
            for (int i = 0; i < 4; i++) a[i]  = As[kk][ty*4 + i];
            #pragma unroll
            for (int j = 0; j < 4; j++) bv[j] = Bs[kk][tx*4 + j];
            #pragma unroll
            for (int i = 0; i < 4; i++)
                #pragma unroll
                for (int j = 0; j < 4; j++) acc[i][j] += a[i]*bv[j];
        }
        __syncthreads();
    }
    #pragma unroll
    for (int i = 0; i < 4; i++) {
        int r = rowBase + ty*4 + i;
        #pragma unroll
        for (int j = 0; j < 4; j++)
            d_kvfull[(size_t)r*Cc + colBase + tx*4 + j] = acc[i][j];
    }
}

// BmatTh[j][r] = kvfull[rr][j]  (fp16, NO 1/N factor), rr = (j<128) ? r : r^256
__global__ void k_bmatT() {
    int idx = blockIdx.x * 256 + threadIdx.x;   // 512*256 total
    int r = idx >> 8, j = idx & 255;
    int rr = (j < Cc/2) ? r : (r ^ Cc);
    d_BmatTh[(size_t)j*(2*Cc) + r] = __float2half(d_kvfull[(size_t)rr*Cc + j]);
}

// ---------------- z from fp16 qcat (one warp per row) -------------------------
__global__ void k_zrow() {
    int row  = blockIdx.x * 8 + (threadIdx.x >> 5);
    int lane = threadIdx.x & 31;
    const __half2* q = (const __half2*)(d_qcat + (size_t)row * (2*Cc));
    float s1 = 0.f, s2 = 0.f;
    #pragma unroll
    for (int t = 0; t < 8; t++) {
        int c2 = lane + t*32;           // half2 index 0..255
        float2 qf = __half22float2(q[c2]);
        int c = 2*c2;
        float k1a = d_kmean[c],       k1b = d_kmean[c+1];
        float k2a = d_kmean[c ^ Cc],  k2b = d_kmean[(c+1) ^ Cc];
        s1 += qf.x*k1a + qf.y*k1b;
        s2 += qf.x*k2a + qf.y*k2b;
    }
    #pragma unroll
    for (int o = 16; o; o >>= 1) {
        s1 += __shfl_xor_sync(0xffffffffu, s1, o);
        s2 += __shfl_xor_sync(0xffffffffu, s2, o);
    }
    if (lane == 0) {
        d_z [row] = 1.0f / (s1 + EPS_Z);
        d_z2[row] = 1.0f / (s2 + EPS_Z);
    }
}

// ---------------- fused depthwise conv + gate + transpose-out ----------------
__global__ void k_convout(const float* __restrict__ wgt, const float* __restrict__ bias,
                          float* __restrict__ out) {
    __shared__ float tile[32][33];
    int b  = blockIdx.z;
    int s0 = blockIdx.x * 32, c0 = blockIdx.y * 32;
    int tx = threadIdx.x, ty = threadIdx.y;
    int ch = c0 + tx;
    float w[9];
    #pragma unroll
    for (int k = 0; k < 9; k++) w[k] = wgt[ch*9 + k];
    float bs = bias[ch];
    #pragma unroll
    for (int pi = ty; pi < 32; pi += 8) {
        int s = s0 + pi;
        int h = s >> 6, wc = s & 63;
        size_t i = (size_t)b*HW + s;
        float center = d_xo[i*Cc + ch];
        float acc = bs;
        #pragma unroll
        for (int kh = 0; kh < 3; kh++) {
            int hh = h + kh - 1;
            if (hh < 0 || hh >= Hh) continue;
            #pragma unroll
            for (int kw = 0; kw < 3; kw++) {
                int ww2 = wc + kw - 1;
                if (ww2 < 0 || ww2 >= Ww) continue;
                acc += w[kh*3 + kw] * d_xo[(i + (kh-1)*Ww + (kw-1))*Cc + ch];
            }
        }
        tile[pi][tx] = (center + acc) * d_g[i*Cc + ch];
    }
    __syncthreads();
    #pragma unroll
    for (int r = ty; r < 32; r += 8)
        out[((size_t)(b*Cc + c0 + r))*HW + s0 + tx] = tile[tx][r];
}

// ---------------- launch -----------------------------------------------------
extern "C" void kernel_launch(void* const* d_in, const int* in_sizes, int n_in,
                              void* d_out, int out_size)
{
    const float* x       = (const float*)d_in[0];
    const float* units_w = (const float*)d_in[1];
    const float* power   = (const float*)d_in[2];
    const float* g_w     = (const float*)d_in[3];
    const float* g_b     = (const float*)d_in[4];
    const float* dwc_w   = (const float*)d_in[5];
    const float* dwc_b   = (const float*)d_in[6];

    float* out   = (float*)d_out;                  // (B,C,H,W)
    float* score = (float*)d_out + OUT_ELEMS;      // (N, K)

    void *p_xfh, *p_g, *p_xo, *p_qcat, *p_bigBh, *p_bmatTh;
    cudaGetSymbolAddress(&p_xfh,    d_xfh);
    cudaGetSymbolAddress(&p_g,      d_g);
    cudaGetSymbolAddress(&p_xo,     d_xo);
    cudaGetSymbolAddress(&p_qcat,   d_qcat);
    cudaGetSymbolAddress(&p_bigBh,  d_bigBh);
    cudaGetSymbolAddress(&p_bmatTh, d_BmatTh);

    static bool attrSet = false;
    if (!attrSet) {
        cudaFuncSetAttribute(k_mma<3>, cudaFuncAttributeMaxDynamicSharedMemorySize, MMA_SMEM_BYTES);
        cudaFuncSetAttribute(k_mma<2>, cudaFuncAttributeMaxDynamicSharedMemorySize, MMA_SMEM_BYTES);
        attrSet = true;
    }

    k_init<<<(Cc*Cc)/256, 256>>>(power, g_w);
    k_norm_units<<<KD, 256>>>(units_w);
    k_transnorm<<<dim3(HW/32, Bb), 256>>>(x);

    // merged: [g | score] = xfh @ bigB^T  (fp16 mma, fused bias / rinv+argmax)
    k_mma<3><<<dim3((Cc+KD)/128, Nn/128), 256, MMA_SMEM_BYTES>>>(
        (const __half*)p_xfh, (const __half*)p_bigBh, (float*)p_g, score, g_b, Cc, 1.f);

    k_count<<<Nn/256, 256>>>();
    k_scan<<<1, 1024>>>();
    k_fill<<<Nn/256, 256>>>();
    k_update_codes<<<KD, 256>>>(units_w);
    k_kmean<<<dim3(2, 8), 256>>>();
    k_gemm_kv<<<dim3(Cc/64, (2*Cc)/64), 256>>>();
    k_bmatT<<<(2*Cc*Cc)/256, 256>>>();

    k_zrow<<<Nn/8, 256>>>();
    // xo = qcat @ BmatTh^T * z/N   (fp16 mma)
    k_mma<2><<<dim3(Cc/128, Nn/128), 256, MMA_SMEM_BYTES>>>(
        (const __half*)p_qcat, (const __half*)p_bmatTh, (float*)p_xo, nullptr, nullptr, 2*Cc, 1.0f/(float)Nn);

    dim3 tb(32, 8);
    k_convout<<<dim3(HW/32, Cc/32, Bb), tb>>>(dwc_w, dwc_b, out);
}

// round 11
// speedup vs baseline: 4.3167x; 1.0344x over previous
#include <cuda_runtime.h>
#include <cuda_fp16.h>
#include <cstdint>
#include <math.h>

// Problem constants (fixed shapes for this dataset)
#define Bb   8
#define Cc   256
#define Hh   64
#define Ww   64
#define HW   (Hh*Ww)          // 4096
#define Nn   (Bb*HW)          // 32768
#define KD   1024
#define OUT_ELEMS ((size_t)Bb*Cc*HW)   // 8388608

#define EPS_NORM 1e-12f
#define EPS_Z    1e-6f
#define RATE     0.999f

// ---------------- scratch (device globals; no allocation allowed) -----------
__device__ __half d_xfh [(size_t)Nn*Cc];
__device__ float  d_rinv[Nn];
__device__ float  d_g   [(size_t)Nn*Cc];
__device__ float  d_xo  [(size_t)Nn*Cc];
__device__ __half d_qcat[(size_t)Nn*2*Cc];
__device__ __half d_bigBh[(size_t)(Cc+KD)*Cc];  // rows 0-255: g_w; 256-1279: mn0
__device__ float  d_mnew[(size_t)KD*Cc];
__device__ float  d_kk  [(size_t)KD*2*Cc];
__device__ int    d_cnt [KD];
__device__ int    d_off [KD];
__device__ int    d_cur [KD];
__device__ int    d_rowlist[Nn];
__device__ unsigned long long d_best[Nn];
__device__ float  d_p   [Cc];
__device__ float  d_kmean[2*Cc];
__device__ float  d_kvfull[(size_t)2*Cc*Cc];  // 512 x 256
__device__ __half d_BmatTh[(size_t)Cc*2*Cc];  // 256 x 512 (transposed, NO 1/N)
__device__ float  d_z [Nn];
__device__ float  d_z2[Nn];

// ---------------- helpers -----------------------------------------------------
__device__ __forceinline__ void cp_async16(uint32_t smem_dst, const void* gsrc) {
    asm volatile("cp.async.cg.shared.global [%0], [%1], 16;" :: "r"(smem_dst), "l"(gsrc));
}
#define CP_COMMIT() asm volatile("cp.async.commit_group;" ::: "memory")
#define CP_WAIT(n)  asm volatile("cp.async.wait_group %0;" :: "n"(n) : "memory")

__device__ __forceinline__ void ldsm_x4(uint32_t& r0, uint32_t& r1, uint32_t& r2,
                                        uint32_t& r3, uint32_t a) {
    asm volatile("ldmatrix.sync.aligned.m8n8.x4.shared.b16 {%0,%1,%2,%3}, [%4];"
        : "=r"(r0), "=r"(r1), "=r"(r2), "=r"(r3) : "r"(a));
}
__device__ __forceinline__ void ldsm_x2(uint32_t& r0, uint32_t& r1, uint32_t a) {
    asm volatile("ldmatrix.sync.aligned.m8n8.x2.shared.b16 {%0,%1}, [%2];"
        : "=r"(r0), "=r"(r1) : "r"(a));
}

// pow(|v|, p) with sign split: one LG2 + one EX2 for both branches
__device__ __forceinline__ void pow_pair(float v, float p, float& qp, float& qn) {
    float e = exp2f(p * __log2f(fabsf(v)));   // v==0 -> log2=-inf -> e=0
    qp = (v > 0.f) ? e : 0.f;
    qn = (v < 0.f) ? e : 0.f;
}

// ---------------- fp16 mma.sync NT GEMM (3-stage cp.async, KT=64, ldmatrix) --
// MODE 3: merged g+score — C1=d_g (+bias, cols<256), C2=score (*rinv, fused argmax)
// MODE 2: xo — C1=xo, scale by (col<128 ? z : z2) * escale
#define KT       64
#define HSTRIDE  72                          // 64 + 8 pad (144B rows: ldsm conflict-free)
#define TEN_HALVES (128*HSTRIDE)             // one tensor (A or B) per stage
#define STG_HALVES (2*TEN_HALVES)
#define STG_BYTES  (STG_HALVES*2)            // 36864
#define TEN_BYTES  (TEN_HALVES*2)
#define MMA_SMEM_BYTES (3*STG_BYTES)         // 110592

template<int MODE>
__global__ __launch_bounds__(256)
void k_mma(const __half* __restrict__ A, const __half* __restrict__ B,
           float* __restrict__ C1, float* __restrict__ C2,
           const float* __restrict__ bias, int Kd, float escale)
{
    extern __shared__ __half sh[];
    const uint32_t shBase = (uint32_t)__cvta_generic_to_shared(sh);
    int tid  = threadIdx.x;
    int lane = tid & 31, wid = tid >> 5;
    int wm = wid >> 2, wn = wid & 3;       // 2 x 4 warp grid
    int gID = lane >> 2, qd = lane & 3;
    const int rowBase = blockIdx.y * 128;
    const int colBase = blockIdx.x * 128;
    const __half* Agm = A + (size_t)rowBase * Kd;
    const __half* Bgm = B + (size_t)colBase * Kd;

    // per-lane ldmatrix byte offsets within a tensor
    const uint32_t la_off = (uint32_t)(((lane & 15)*HSTRIDE + (lane >> 4)*8) * 2);
    const uint32_t lb_off = (uint32_t)(((lane & 7)*HSTRIDE + ((lane >> 3) & 1)*8) * 2);
    // per-warp row bases (bytes)
    const uint32_t aw_off = (uint32_t)(wm*64*HSTRIDE*2);
    const uint32_t bw_off = (uint32_t)(wn*32*HSTRIDE*2);
    // cp.async per-thread smem offset (bytes): 4 chunks, idx = tid + e*256
    // r = idx>>3, q = idx&7  ->  (r*HSTRIDE + q*8)*2

    float acc[4][4][4];
    #pragma unroll
    for (int i = 0; i < 4; i++)
        #pragma unroll
        for (int j = 0; j < 4; j++)
            #pragma unroll
            for (int t = 0; t < 4; t++) acc[i][j][t] = 0.f;

    const int nKT = Kd >> 6;   // KT = 64

    // prologue: stages 0,1
    #pragma unroll
    for (int s = 0; s < 2; s++) {
        uint32_t stA = shBase + s*STG_BYTES;
        uint32_t stB = stA + TEN_BYTES;
        int koff = s * KT;
        #pragma unroll
        for (int e = 0; e < 4; e++) {
            int idx = tid + e*256;
            int r = idx >> 3, q = idx & 7;
            uint32_t so = (uint32_t)((r*HSTRIDE + q*8) * 2);
            cp_async16(stA + so, Agm + (size_t)r*Kd + koff + q*8);
            cp_async16(stB + so, Bgm + (size_t)r*Kd + koff + q*8);
        }
        CP_COMMIT();
    }

    int stCur = 0, stPre = 2;
    for (int kt = 0; kt < nKT; kt++) {
        if (kt < nKT - 1) { CP_WAIT(1); } else { CP_WAIT(0); }
        __syncthreads();
        if (kt + 2 < nKT) {
            uint32_t stA = shBase + stPre*STG_BYTES;
            uint32_t stB = stA + TEN_BYTES;
            int koff = (kt + 2) * KT;
            #pragma unroll
            for (int e = 0; e < 4; e++) {
                int idx = tid + e*256;
                int r = idx >> 3, q = idx & 7;
                uint32_t so = (uint32_t)((r*HSTRIDE + q*8) * 2);
                cp_async16(stA + so, Agm + (size_t)r*Kd + koff + q*8);
                cp_async16(stB + so, Bgm + (size_t)r*Kd + koff + q*8);
            }
            CP_COMMIT();
        }

        uint32_t aBase = shBase + stCur*STG_BYTES + aw_off + la_off;
        uint32_t bBase = shBase + stCur*STG_BYTES + TEN_BYTES + bw_off + lb_off;
        #pragma unroll
        for (int ks = 0; ks < 4; ks++) {
            uint32_t kOff = (uint32_t)(ks * 16 * 2);   // 16 halves along k
            uint32_t bf[4][2];
            #pragma unroll
            for (int j = 0; j < 4; j++)
                ldsm_x2(bf[j][0], bf[j][1], bBase + (uint32_t)(j*8*HSTRIDE*2) + kOff);
            #pragma unroll
            for (int i = 0; i < 4; i++) {
                uint32_t a0, a1, a2, a3;
                ldsm_x4(a0, a1, a2, a3, aBase + (uint32_t)(i*16*HSTRIDE*2) + kOff);
                #pragma unroll
                for (int j = 0; j < 4; j++) {
                    asm volatile(
                        "mma.sync.aligned.m16n8k16.row.col.f32.f16.f16.f32 "
                        "{%0,%1,%2,%3}, {%4,%5,%6,%7}, {%8,%9}, {%0,%1,%2,%3};"
                        : "+f"(acc[i][j][0]), "+f"(acc[i][j][1]),
                          "+f"(acc[i][j][2]), "+f"(acc[i][j][3])
                        : "r"(a0), "r"(a1), "r"(a2), "r"(a3),
                          "r"(bf[j][0]), "r"(bf[j][1]));
                }
            }
        }
        stCur++; if (stCur == 3) stCur = 0;
        stPre++; if (stPre == 3) stPre = 0;
    }

    // ---- epilogue ----
    bool scoreTile = (MODE == 3) && (colBase >= Cc);
    #pragma unroll
    for (int i = 0; i < 4; i++) {
        int r0 = rowBase + wm*64 + i*16 + gID;
        int r1 = r0 + 8;
        float s0 = 1.f, s1 = 1.f;
        if (MODE == 2) {
            bool firstHalf = (colBase < Cc/2);
            s0 = (firstHalf ? d_z[r0] : d_z2[r0]) * escale;
            s1 = (firstHalf ? d_z[r1] : d_z2[r1]) * escale;
        } else if (scoreTile) {
            s0 = d_rinv[r0];
            s1 = d_rinv[r1];
        }
        unsigned long long best0 = 0ull, best1 = 0ull;
        #pragma unroll
        for (int j = 0; j < 4; j++) {
            int c0 = colBase + wn*32 + j*8 + 2*qd;
            float v00 = acc[i][j][0], v01 = acc[i][j][1];
            float v10 = acc[i][j][2], v11 = acc[i][j][3];
            if (MODE == 2) {
                v00 *= s0; v01 *= s0; v10 *= s1; v11 *= s1;
                *(float2*)(C1 + (size_t)r0*Cc + c0) = make_float2(v00, v01);
                *(float2*)(C1 + (size_t)r1*Cc + c0) = make_float2(v10, v11);
            } else if (!scoreTile) {
                float b0 = bias[c0], b1 = bias[c0+1];
                v00 += b0; v01 += b1; v10 += b0; v11 += b1;
                *(float2*)(C1 + (size_t)r0*Cc + c0) = make_float2(v00, v01);
                *(float2*)(C1 + (size_t)r1*Cc + c0) = make_float2(v10, v11);
            } else {
                int cs = c0 - Cc;
                v00 *= s0; v01 *= s0; v10 *= s1; v11 *= s1;
                *(float2*)(C2 + (size_t)r0*KD + cs) = make_float2(v00, v01);
                *(float2*)(C2 + (size_t)r1*KD + cs) = make_float2(v10, v11);
                uint32_t k00 = __float_as_uint(v00); k00 ^= (k00 & 0x80000000u) ? 0xFFFFFFFFu : 0x80000000u;
                uint32_t k01 = __float_as_uint(v01); k01 ^= (k01 & 0x80000000u) ? 0xFFFFFFFFu : 0x80000000u;
                uint32_t k10 = __float_as_uint(v10); k10 ^= (k10 & 0x80000000u) ? 0xFFFFFFFFu : 0x80000000u;
                uint32_t k11 = __float_as_uint(v11); k11 ^= (k11 & 0x80000000u) ? 0xFFFFFFFFu : 0x80000000u;
                unsigned long long p00 = ((unsigned long long)k00 << 32) | (uint32_t)(KD-1-cs);
                unsigned long long p01 = ((unsigned long long)k01 << 32) | (uint32_t)(KD-2-cs);
                unsigned long long p10 = ((unsigned long long)k10 << 32) | (uint32_t)(KD-1-cs);
                unsigned long long p11 = ((unsigned long long)k11 << 32) | (uint32_t)(KD-2-cs);
                if (p01 > p00) p00 = p01;
                if (p11 > p10) p10 = p11;
                if (p00 > best0) best0 = p00;
                if (p10 > best1) best1 = p10;
            }
        }
        if (scoreTile) {
            #pragma unroll
            for (int o = 1; o <= 2; o <<= 1) {
                unsigned long long t0 = __shfl_xor_sync(0xffffffffu, best0, o);
                unsigned long long t1 = __shfl_xor_sync(0xffffffffu, best1, o);
                if (t0 > best0) best0 = t0;
                if (t1 > best1) best1 = t1;
            }
            if (qd == 0) {
                atomicMax(&d_best[r0], best0);
                atomicMax(&d_best[r1], best1);
            }
        }
    }
}

// ---------------- merged init: gw convert into bigB + p + zero best/cnt/kmean
__global__ void k_init(const float* __restrict__ power, const float* __restrict__ gw) {
    int idx = blockIdx.x * 256 + threadIdx.x;      // 65536 threads
    d_bigBh[idx] = __float2half(gw[idx]);          // rows 0-255 of bigB
    if (idx < Nn) d_best[idx] = 0ull;
    if (idx < KD) d_cnt[idx] = 0;
    if (idx < 2*Cc) d_kmean[idx] = 0.f;
    if (idx < Cc) {
        float pw = power[idx];
        d_p[idx] = 1.0f + 4.0f / (1.0f + __expf(-pw));
    }
}

// one block per codebook row -> normalized fp16 into bigB rows 256..1279
__global__ void k_norm_units(const float* __restrict__ uw) {
    __shared__ float red[256];
    int k = blockIdx.x, ch = threadIdx.x;
    float v = uw[(size_t)k*Cc + ch];
    red[ch] = v*v; __syncthreads();
    for (int o = 128; o; o >>= 1) {
        if (ch < o) red[ch] += red[ch+o];
        __syncthreads();
    }
    float inv = 1.0f / fmaxf(sqrtf(red[0]), EPS_NORM);
    d_bigBh[(size_t)(Cc + k)*Cc + ch] = __float2half(v*inv);
}

// fused: x (B,C,HW) -> xfh (fp16) + rinv + power features qcat (fp16)
__global__ __launch_bounds__(256)
void k_transnorm(const float* __restrict__ x) {
    __shared__ float tile[256][33];
    int b  = blockIdx.y;
    int s0 = blockIdx.x * 32;
    int tid = threadIdx.x;
    int tx = tid & 31, ty = tid >> 5;
    for (int c = ty; c < Cc; c += 8)
        tile[c][tx] = x[((size_t)(b*Cc + c))*HW + s0 + tx];
    __syncthreads();
    int lane = tx, wrp = ty;
    #pragma unroll
    for (int t = 0; t < 4; t++) {
        int p = wrp + t*8;
        float vals[8];
        float ss = 0.f;
        #pragma unroll
        for (int j = 0; j < 8; j++) {
            float v = tile[lane + j*32][p];
            vals[j] = v;
            ss += v*v;
        }
        #pragma unroll
        for (int o = 16; o; o >>= 1) ss += __shfl_xor_sync(0xffffffffu, ss, o);
        float inv = 1.0f / fmaxf(sqrtf(ss), EPS_NORM);
        size_t row = (size_t)b*HW + s0 + p;
        if (lane == 0) d_rinv[row] = inv;
        #pragma unroll
        for (int j = 0; j < 8; j++) {
            int c = lane + j*32;
            float v  = vals[j];
            float vn = v * inv;
            d_xfh[row*Cc + c] = __float2half(v);
            float qp, qn;
            pow_pair(vn, d_p[c], qp, qn);
            d_qcat[row*(2*Cc) + c]      = __float2half(qp);
            d_qcat[row*(2*Cc) + Cc + c] = __float2half(qn);
        }
    }
}

// ---------------- counting-sort EMA path -------------------------------------
__device__ __forceinline__ int best_code(unsigned long long b) {
    return KD - 1 - (int)(uint32_t)(b & 0xFFFFFFFFull);
}

__global__ void k_count() {
    int idx = blockIdx.x * 256 + threadIdx.x;
    atomicAdd(&d_cnt[best_code(d_best[idx])], 1);
}

__global__ void k_scan() {   // 1 block, 1024 threads: exclusive scan
    __shared__ int s[1024];
    int t = threadIdx.x;
    int v = d_cnt[t];
    s[t] = v; __syncthreads();
    for (int o = 1; o < 1024; o <<= 1) {
        int add = (t >= o) ? s[t-o] : 0;
        __syncthreads();
        s[t] += add;
        __syncthreads();
    }
    d_off[t] = s[t] - v;
    d_cur[t] = s[t] - v;
}

__global__ void k_fill() {
    int idx = blockIdx.x * 256 + threadIdx.x;
    int code = best_code(d_best[idx]);
    int pos = atomicAdd(&d_cur[code], 1);
    d_rowlist[pos] = idx;
}

__global__ void k_update_codes(const float* __restrict__ uw) {
    __shared__ float red[256];
    int k = blockIdx.x, ch = threadIdx.x;
    int cnt = d_cnt[k], off = d_off[k];
    float sum = 0.f;
    for (int t = 0; t < cnt; t++) {
        int row = d_rowlist[off + t];
        sum += __half2float(d_xfh[(size_t)row*Cc + ch]);
    }
    float em = sum / ((float)cnt + EPS_Z);
    float mv = uw[(size_t)k*Cc + ch]*RATE + em*(1.0f - RATE);
    d_mnew[(size_t)k*Cc + ch] = mv;
    red[ch] = mv*mv; __syncthreads();
    for (int o = 128; o; o >>= 1) {
        if (ch < o) red[ch] += red[ch+o];
        __syncthreads();
    }
    float inv = 1.0f / fmaxf(sqrtf(red[0]), EPS_NORM);
    float mnv = mv*inv;
    float qp, qn;
    pow_pair(mnv, d_p[ch], qp, qn);
    d_kk[(size_t)k*(2*Cc) + ch]      = qp;
    d_kk[(size_t)k*(2*Cc) + Cc + ch] = qn;
}

__global__ void k_kmean() {  // grid (2, 8), 256 threads
    int col = blockIdx.x * 256 + threadIdx.x;
    int r0 = blockIdx.y * 128;
    float s = 0.f;
    for (int r = r0; r < r0 + 128; r++) s += d_kk[(size_t)r*(2*Cc) + col];
    atomicAdd(&d_kmean[col], s * (1.0f / KD));
}

// KVfull[512,256] = kk^T (512x1024) @ mnew (1024x256) — small, fp32
__global__ __launch_bounds__(256)
void k_gemm_kv()
{
    __shared__ float As[16][68];
    __shared__ float Bs[16][68];
    int tid = threadIdx.x;
    int tx = tid & 15, ty = tid >> 4;
    int rowBase = blockIdx.y * 64, colBase = blockIdx.x * 64;
    float acc[4][4] = {};
    for (int k0 = 0; k0 < KD; k0 += 16) {
        #pragma unroll
        for (int e = 0; e < 4; e++) {
            int t = tid + e*256;
            int kk = t >> 6, r = t & 63;
            As[kk][r] = d_kk[(size_t)(k0 + kk)*(2*Cc) + rowBase + r];
        }
        #pragma unroll
        for (int e = 0; e < 4; e++) {
            int t = tid + e*256;
            int kk = t >> 6, c = t & 63;
            Bs[kk][c] = d_mnew[(size_t)(k0 + kk)*Cc + colBase + c];
        }
        __syncthreads();
        #pragma unroll
        for (int kk = 0; kk < 16; kk++) {
            float a[4], bv[4];
            #pragma unroll
            for (int i = 0; i < 4; i++) a[i]  = As[kk][ty*4 + i];
            #pragma unroll
            for (int j = 0; j < 4; j++) bv[j] = Bs[kk][tx*4 + j];
            #pragma unroll
            for (int i = 0; i < 4; i++)
                #pragma unroll
                for (int j = 0; j < 4; j++) acc[i][j] += a[i]*bv[j];
        }
        __syncthreads();
    }
    #pragma unroll
    for (int i = 0; i < 4; i++) {
        int r = rowBase + ty*4 + i;
        #pragma unroll
        for (int j = 0; j < 4; j++)
            d_kvfull[(size_t)r*Cc + colBase + tx*4 + j] = acc[i][j];
    }
}

// BmatTh[j][r] = kvfull[rr][j]  (fp16, NO 1/N factor), rr = (j<128) ? r : r^256
__global__ void k_bmatT() {
    int idx = blockIdx.x * 256 + threadIdx.x;   // 512*256 total
    int r = idx >> 8, j = idx & 255;
    int rr = (j < Cc/2) ? r : (r ^ Cc);
    d_BmatTh[(size_t)j*(2*Cc) + r] = __float2half(d_kvfull[(size_t)rr*Cc + j]);
}

// ---------------- z from fp16 qcat (one warp per row) -------------------------
__global__ void k_zrow() {
    int row  = blockIdx.x * 8 + (threadIdx.x >> 5);
    int lane = threadIdx.x & 31;
    const __half2* q = (const __half2*)(d_qcat + (size_t)row * (2*Cc));
    float s1 = 0.f, s2 = 0.f;
    #pragma unroll
    for (int t = 0; t < 8; t++) {
        int c2 = lane + t*32;           // half2 index 0..255
        float2 qf = __half22float2(q[c2]);
        int c = 2*c2;
        float k1a = d_kmean[c],       k1b = d_kmean[c+1];
        float k2a = d_kmean[c ^ Cc],  k2b = d_kmean[(c+1) ^ Cc];
        s1 += qf.x*k1a + qf.y*k1b;
        s2 += qf.x*k2a + qf.y*k2b;
    }
    #pragma unroll
    for (int o = 16; o; o >>= 1) {
        s1 += __shfl_xor_sync(0xffffffffu, s1, o);
        s2 += __shfl_xor_sync(0xffffffffu, s2, o);
    }
    if (lane == 0) {
        d_z [row] = 1.0f / (s1 + EPS_Z);
        d_z2[row] = 1.0f / (s2 + EPS_Z);
    }
}

// ---------------- fused depthwise conv + gate + transpose-out ----------------
__global__ void k_convout(const float* __restrict__ wgt, const float* __restrict__ bias,
                          float* __restrict__ out) {
    __shared__ float tile[32][33];
    int b  = blockIdx.z;
    int s0 = blockIdx.x * 32, c0 = blockIdx.y * 32;
    int tx = threadIdx.x, ty = threadIdx.y;
    int ch = c0 + tx;
    float w[9];
    #pragma unroll
    for (int k = 0; k < 9; k++) w[k] = wgt[ch*9 + k];
    float bs = bias[ch];
    #pragma unroll
    for (int pi = ty; pi < 32; pi += 8) {
        int s = s0 + pi;
        int h = s >> 6, wc = s & 63;
        size_t i = (size_t)b*HW + s;
        float center = d_xo[i*Cc + ch];
        float acc = bs;
        #pragma unroll
        for (int kh = 0; kh < 3; kh++) {
            int hh = h + kh - 1;
            if (hh < 0 || hh >= Hh) continue;
            #pragma unroll
            for (int kw = 0; kw < 3; kw++) {
                int ww2 = wc + kw - 1;
                if (ww2 < 0 || ww2 >= Ww) continue;
                acc += w[kh*3 + kw] * d_xo[(i + (kh-1)*Ww + (kw-1))*Cc + ch];
            }
        }
        tile[pi][tx] = (center + acc) * d_g[i*Cc + ch];
    }
    __syncthreads();
    #pragma unroll
    for (int r = ty; r < 32; r += 8)
        out[((size_t)(b*Cc + c0 + r))*HW + s0 + tx] = tile[tx][r];
}

// ---------------- launch -----------------------------------------------------
extern "C" void kernel_launch(void* const* d_in, const int* in_sizes, int n_in,
                              void* d_out, int out_size)
{
    const float* x       = (const float*)d_in[0];
    const float* units_w = (const float*)d_in[1];
    const float* power   = (const float*)d_in[2];
    const float* g_w     = (const float*)d_in[3];
    const float* g_b     = (const float*)d_in[4];
    const float* dwc_w   = (const float*)d_in[5];
    const float* dwc_b   = (const float*)d_in[6];

    float* out   = (float*)d_out;                  // (B,C,H,W)
    float* score = (float*)d_out + OUT_ELEMS;      // (N, K)

    void *p_xfh, *p_g, *p_xo, *p_qcat, *p_bigBh, *p_bmatTh;
    cudaGetSymbolAddress(&p_xfh,    d_xfh);
    cudaGetSymbolAddress(&p_g,      d_g);
    cudaGetSymbolAddress(&p_xo,     d_xo);
    cudaGetSymbolAddress(&p_qcat,   d_qcat);
    cudaGetSymbolAddress(&p_bigBh,  d_bigBh);
    cudaGetSymbolAddress(&p_bmatTh, d_BmatTh);

    static bool attrSet = false;
    if (!attrSet) {
        cudaFuncSetAttribute(k_mma<3>, cudaFuncAttributeMaxDynamicSharedMemorySize, MMA_SMEM_BYTES);
        cudaFuncSetAttribute(k_mma<2>, cudaFuncAttributeMaxDynamicSharedMemorySize, MMA_SMEM_BYTES);
        attrSet = true;
    }

    k_init<<<(Cc*Cc)/256, 256>>>(power, g_w);
    k_norm_units<<<KD, 256>>>(units_w);
    k_transnorm<<<dim3(HW/32, Bb), 256>>>(x);

    // merged: [g | score] = xfh @ bigB^T  (fp16 mma, fused bias / rinv+argmax)
    k_mma<3><<<dim3((Cc+KD)/128, Nn/128), 256, MMA_SMEM_BYTES>>>(
        (const __half*)p_xfh, (const __half*)p_bigBh, (float*)p_g, score, g_b, Cc, 1.f);

    k_count<<<Nn/256, 256>>>();
    k_scan<<<1, 1024>>>();
    k_fill<<<Nn/256, 256>>>();
    k_update_codes<<<KD, 256>>>(units_w);
    k_kmean<<<dim3(2, 8), 256>>>();
    k_gemm_kv<<<dim3(Cc/64, (2*Cc)/64), 256>>>();
    k_bmatT<<<(2*Cc*Cc)/256, 256>>>();

    k_zrow<<<Nn/8, 256>>>();
    // xo = qcat @ BmatTh^T * z/N   (fp16 mma)
    k_mma<2><<<dim3(Cc/128, Nn/128), 256, MMA_SMEM_BYTES>>>(
        (const __half*)p_qcat, (const __half*)p_bmatTh, (float*)p_xo, nullptr, nullptr, 2*Cc, 1.0f/(float)Nn);

    dim3 tb(32, 8);
    k_convout<<<dim3(HW/32, Cc/32, Bb), tb>>>(dwc_w, dwc_b, out);
}

// round 12
// speedup vs baseline: 4.4476x; 1.0303x over previous
#include <cuda_runtime.h>
#include <cuda_fp16.h>
#include <cstdint>
#include <math.h>

// Problem constants (fixed shapes for this dataset)
#define Bb   8
#define Cc   256
#define Hh   64
#define Ww   64
#define HW   (Hh*Ww)          // 4096
#define Nn   (Bb*HW)          // 32768
#define KD   1024
#define OUT_ELEMS ((size_t)Bb*Cc*HW)   // 8388608

#define EPS_NORM 1e-12f
#define EPS_Z    1e-6f
#define RATE     0.999f

// ---------------- scratch (device globals; no allocation allowed) -----------
__device__ __half d_xfh [(size_t)Nn*Cc];
__device__ float  d_rinv[Nn];
__device__ float  d_g   [(size_t)Nn*Cc];
__device__ float  d_xo  [(size_t)Nn*Cc];
__device__ __half d_qcat[(size_t)Nn*2*Cc];
__device__ __half d_bigBh[(size_t)(Cc+KD)*Cc];  // rows 0-255: g_w; 256-1279: mn0
__device__ float  d_mnew[(size_t)KD*Cc];
__device__ float  d_kk  [(size_t)KD*2*Cc];
__device__ int    d_cnt [KD];
__device__ int    d_off [KD];
__device__ int    d_cur [KD];
__device__ int    d_rowlist[Nn];
__device__ unsigned long long d_best[Nn];
__device__ float  d_p   [Cc];
__device__ float  d_kmean[2*Cc];
__device__ __half d_BmatTh[(size_t)Cc*2*Cc];  // 256 x 512 (transposed, NO 1/N)
__device__ float  d_z [Nn];
__device__ float  d_z2[Nn];

// ---------------- helpers -----------------------------------------------------
__device__ __forceinline__ void cp_async16(uint32_t smem_dst, const void* gsrc) {
    asm volatile("cp.async.cg.shared.global [%0], [%1], 16;" :: "r"(smem_dst), "l"(gsrc));
}
#define CP_COMMIT() asm volatile("cp.async.commit_group;" ::: "memory")
#define CP_WAIT(n)  asm volatile("cp.async.wait_group %0;" :: "n"(n) : "memory")

__device__ __forceinline__ void ldsm_x4(uint32_t& r0, uint32_t& r1, uint32_t& r2,
                                        uint32_t& r3, uint32_t a) {
    asm volatile("ldmatrix.sync.aligned.m8n8.x4.shared.b16 {%0,%1,%2,%3}, [%4];"
        : "=r"(r0), "=r"(r1), "=r"(r2), "=r"(r3) : "r"(a));
}
__device__ __forceinline__ void ldsm_x2(uint32_t& r0, uint32_t& r1, uint32_t a) {
    asm volatile("ldmatrix.sync.aligned.m8n8.x2.shared.b16 {%0,%1}, [%2];"
        : "=r"(r0), "=r"(r1) : "r"(a));
}

// pow(|v|, p) with sign split: one LG2 + one EX2 for both branches
__device__ __forceinline__ void pow_pair(float v, float p, float& qp, float& qn) {
    float e = exp2f(p * __log2f(fabsf(v)));   // v==0 -> log2=-inf -> e=0
    qp = (v > 0.f) ? e : 0.f;
    qn = (v < 0.f) ? e : 0.f;
}

// ---------------- fp16 mma.sync NT GEMM (3-stage cp.async, KT=64, ldmatrix) --
// MODE 3: merged g+score — C1=d_g (+bias, cols<256), C2=score (*rinv, fused argmax)
// MODE 2: xo — C1=xo, scale by (col<128 ? z : z2) * escale
#define KT       64
#define HSTRIDE  72                          // 64 + 8 pad (144B rows: ldsm conflict-free)
#define TEN_HALVES (128*HSTRIDE)             // one tensor (A or B) per stage
#define STG_HALVES (2*TEN_HALVES)
#define STG_BYTES  (STG_HALVES*2)            // 36864
#define TEN_BYTES  (TEN_HALVES*2)
#define MMA_SMEM_BYTES (3*STG_BYTES)         // 110592

template<int MODE>
__global__ __launch_bounds__(256)
void k_mma(const __half* __restrict__ A, const __half* __restrict__ B,
           float* __restrict__ C1, float* __restrict__ C2,
           const float* __restrict__ bias, int Kd, float escale)
{
    extern __shared__ __half sh[];
    const uint32_t shBase = (uint32_t)__cvta_generic_to_shared(sh);
    int tid  = threadIdx.x;
    int lane = tid & 31, wid = tid >> 5;
    int wm = wid >> 2, wn = wid & 3;       // 2 x 4 warp grid
    int gID = lane >> 2, qd = lane & 3;
    const int rowBase = blockIdx.y * 128;
    const int colBase = blockIdx.x * 128;
    const __half* Agm = A + (size_t)rowBase * Kd;
    const __half* Bgm = B + (size_t)colBase * Kd;

    // per-lane ldmatrix byte offsets within a tensor
    const uint32_t la_off = (uint32_t)(((lane & 15)*HSTRIDE + (lane >> 4)*8) * 2);
    const uint32_t lb_off = (uint32_t)(((lane & 7)*HSTRIDE + ((lane >> 3) & 1)*8) * 2);
    const uint32_t aw_off = (uint32_t)(wm*64*HSTRIDE*2);
    const uint32_t bw_off = (uint32_t)(wn*32*HSTRIDE*2);

    float acc[4][4][4];
    #pragma unroll
    for (int i = 0; i < 4; i++)
        #pragma unroll
        for (int j = 0; j < 4; j++)
            #pragma unroll
            for (int t = 0; t < 4; t++) acc[i][j][t] = 0.f;

    const int nKT = Kd >> 6;   // KT = 64

    // prologue: stages 0,1
    #pragma unroll
    for (int s = 0; s < 2; s++) {
        uint32_t stA = shBase + s*STG_BYTES;
        uint32_t stB = stA + TEN_BYTES;
        int koff = s * KT;
        #pragma unroll
        for (int e = 0; e < 4; e++) {
            int idx = tid + e*256;
            int r = idx >> 3, q = idx & 7;
            uint32_t so = (uint32_t)((r*HSTRIDE + q*8) * 2);
            cp_async16(stA + so, Agm + (size_t)r*Kd + koff + q*8);
            cp_async16(stB + so, Bgm + (size_t)r*Kd + koff + q*8);
        }
        CP_COMMIT();
    }

    int stCur = 0, stPre = 2;
    for (int kt = 0; kt < nKT; kt++) {
        if (kt < nKT - 1) { CP_WAIT(1); } else { CP_WAIT(0); }
        __syncthreads();
        if (kt + 2 < nKT) {
            uint32_t stA = shBase + stPre*STG_BYTES;
            uint32_t stB = stA + TEN_BYTES;
            int koff = (kt + 2) * KT;
            #pragma unroll
            for (int e = 0; e < 4; e++) {
                int idx = tid + e*256;
                int r = idx >> 3, q = idx & 7;
                uint32_t so = (uint32_t)((r*HSTRIDE + q*8) * 2);
                cp_async16(stA + so, Agm + (size_t)r*Kd + koff + q*8);
                cp_async16(stB + so, Bgm + (size_t)r*Kd + koff + q*8);
            }
            CP_COMMIT();
        }

        uint32_t aBase = shBase + stCur*STG_BYTES + aw_off + la_off;
        uint32_t bBase = shBase + stCur*STG_BYTES + TEN_BYTES + bw_off + lb_off;
        #pragma unroll
        for (int ks = 0; ks < 4; ks++) {
            uint32_t kOff = (uint32_t)(ks * 16 * 2);
            // batch-issue ALL fragment loads first (LSU pipelines them),
            // then run 64 MMAs with no interleaved LDS dependencies.
            uint32_t bf[4][2];
            uint32_t af[4][4];
            #pragma unroll
            for (int j = 0; j < 4; j++)
                ldsm_x2(bf[j][0], bf[j][1], bBase + (uint32_t)(j*8*HSTRIDE*2) + kOff);
            #pragma unroll
            for (int i = 0; i < 4; i++)
                ldsm_x4(af[i][0], af[i][1], af[i][2], af[i][3],
                        aBase + (uint32_t)(i*16*HSTRIDE*2) + kOff);
            #pragma unroll
            for (int i = 0; i < 4; i++) {
                #pragma unroll
                for (int j = 0; j < 4; j++) {
                    asm volatile(
                        "mma.sync.aligned.m16n8k16.row.col.f32.f16.f16.f32 "
                        "{%0,%1,%2,%3}, {%4,%5,%6,%7}, {%8,%9}, {%0,%1,%2,%3};"
                        : "+f"(acc[i][j][0]), "+f"(acc[i][j][1]),
                          "+f"(acc[i][j][2]), "+f"(acc[i][j][3])
                        : "r"(af[i][0]), "r"(af[i][1]), "r"(af[i][2]), "r"(af[i][3]),
                          "r"(bf[j][0]), "r"(bf[j][1]));
                }
            }
        }
        stCur++; if (stCur == 3) stCur = 0;
        stPre++; if (stPre == 3) stPre = 0;
    }

    // ---- epilogue ----
    bool scoreTile = (MODE == 3) && (colBase >= Cc);
    #pragma unroll
    for (int i = 0; i < 4; i++) {
        int r0 = rowBase + wm*64 + i*16 + gID;
        int r1 = r0 + 8;
        float s0 = 1.f, s1 = 1.f;
        if (MODE == 2) {
            bool firstHalf = (colBase < Cc/2);
            s0 = (firstHalf ? d_z[r0] : d_z2[r0]) * escale;
            s1 = (firstHalf ? d_z[r1] : d_z2[r1]) * escale;
        } else if (scoreTile) {
            s0 = d_rinv[r0];
            s1 = d_rinv[r1];
        }
        unsigned long long best0 = 0ull, best1 = 0ull;
        #pragma unroll
        for (int j = 0; j < 4; j++) {
            int c0 = colBase + wn*32 + j*8 + 2*qd;
            float v00 = acc[i][j][0], v01 = acc[i][j][1];
            float v10 = acc[i][j][2], v11 = acc[i][j][3];
            if (MODE == 2) {
                v00 *= s0; v01 *= s0; v10 *= s1; v11 *= s1;
                *(float2*)(C1 + (size_t)r0*Cc + c0) = make_float2(v00, v01);
                *(float2*)(C1 + (size_t)r1*Cc + c0) = make_float2(v10, v11);
            } else if (!scoreTile) {
                float b0 = bias[c0], b1 = bias[c0+1];
                v00 += b0; v01 += b1; v10 += b0; v11 += b1;
                *(float2*)(C1 + (size_t)r0*Cc + c0) = make_float2(v00, v01);
                *(float2*)(C1 + (size_t)r1*Cc + c0) = make_float2(v10, v11);
            } else {
                int cs = c0 - Cc;
                v00 *= s0; v01 *= s0; v10 *= s1; v11 *= s1;
                *(float2*)(C2 + (size_t)r0*KD + cs) = make_float2(v00, v01);
                *(float2*)(C2 + (size_t)r1*KD + cs) = make_float2(v10, v11);
                uint32_t k00 = __float_as_uint(v00); k00 ^= (k00 & 0x80000000u) ? 0xFFFFFFFFu : 0x80000000u;
                uint32_t k01 = __float_as_uint(v01); k01 ^= (k01 & 0x80000000u) ? 0xFFFFFFFFu : 0x80000000u;
                uint32_t k10 = __float_as_uint(v10); k10 ^= (k10 & 0x80000000u) ? 0xFFFFFFFFu : 0x80000000u;
                uint32_t k11 = __float_as_uint(v11); k11 ^= (k11 & 0x80000000u) ? 0xFFFFFFFFu : 0x80000000u;
                unsigned long long p00 = ((unsigned long long)k00 << 32) | (uint32_t)(KD-1-cs);
                unsigned long long p01 = ((unsigned long long)k01 << 32) | (uint32_t)(KD-2-cs);
                unsigned long long p10 = ((unsigned long long)k10 << 32) | (uint32_t)(KD-1-cs);
                unsigned long long p11 = ((unsigned long long)k11 << 32) | (uint32_t)(KD-2-cs);
                if (p01 > p00) p00 = p01;
                if (p11 > p10) p10 = p11;
                if (p00 > best0) best0 = p00;
                if (p10 > best1) best1 = p10;
            }
        }
        if (scoreTile) {
            #pragma unroll
            for (int o = 1; o <= 2; o <<= 1) {
                unsigned long long t0 = __shfl_xor_sync(0xffffffffu, best0, o);
                unsigned long long t1 = __shfl_xor_sync(0xffffffffu, best1, o);
                if (t0 > best0) best0 = t0;
                if (t1 > best1) best1 = t1;
            }
            if (qd == 0) {
                atomicMax(&d_best[r0], best0);
                atomicMax(&d_best[r1], best1);
            }
        }
    }
}

// ---------------- merged init: gw convert into bigB + p + zero best/cnt/kmean
__global__ void k_init(const float* __restrict__ power, const float* __restrict__ gw) {
    int idx = blockIdx.x * 256 + threadIdx.x;      // 65536 threads
    d_bigBh[idx] = __float2half(gw[idx]);          // rows 0-255 of bigB
    if (idx < Nn) d_best[idx] = 0ull;
    if (idx < KD) d_cnt[idx] = 0;
    if (idx < 2*Cc) d_kmean[idx] = 0.f;
    if (idx < Cc) {
        float pw = power[idx];
        d_p[idx] = 1.0f + 4.0f / (1.0f + __expf(-pw));
    }
}

// one block per codebook row -> normalized fp16 into bigB rows 256..1279
__global__ void k_norm_units(const float* __restrict__ uw) {
    __shared__ float red[256];
    int k = blockIdx.x, ch = threadIdx.x;
    float v = uw[(size_t)k*Cc + ch];
    red[ch] = v*v; __syncthreads();
    for (int o = 128; o; o >>= 1) {
        if (ch < o) red[ch] += red[ch+o];
        __syncthreads();
    }
    float inv = 1.0f / fmaxf(sqrtf(red[0]), EPS_NORM);
    d_bigBh[(size_t)(Cc + k)*Cc + ch] = __float2half(v*inv);
}

// fused: x (B,C,HW) -> xfh (fp16) + rinv + power features qcat (fp16)
__global__ __launch_bounds__(256)
void k_transnorm(const float* __restrict__ x) {
    __shared__ float tile[256][33];
    int b  = blockIdx.y;
    int s0 = blockIdx.x * 32;
    int tid = threadIdx.x;
    int tx = tid & 31, ty = tid >> 5;
    for (int c = ty; c < Cc; c += 8)
        tile[c][tx] = x[((size_t)(b*Cc + c))*HW + s0 + tx];
    __syncthreads();
    int lane = tx, wrp = ty;
    #pragma unroll
    for (int t = 0; t < 4; t++) {
        int p = wrp + t*8;
        float vals[8];
        float ss = 0.f;
        #pragma unroll
        for (int j = 0; j < 8; j++) {
            float v = tile[lane + j*32][p];
            vals[j] = v;
            ss += v*v;
        }
        #pragma unroll
        for (int o = 16; o; o >>= 1) ss += __shfl_xor_sync(0xffffffffu, ss, o);
        float inv = 1.0f / fmaxf(sqrtf(ss), EPS_NORM);
        size_t row = (size_t)b*HW + s0 + p;
        if (lane == 0) d_rinv[row] = inv;
        #pragma unroll
        for (int j = 0; j < 8; j++) {
            int c = lane + j*32;
            float v  = vals[j];
            float vn = v * inv;
            d_xfh[row*Cc + c] = __float2half(v);
            float qp, qn;
            pow_pair(vn, d_p[c], qp, qn);
            d_qcat[row*(2*Cc) + c]      = __float2half(qp);
            d_qcat[row*(2*Cc) + Cc + c] = __float2half(qn);
        }
    }
}

// ---------------- counting-sort EMA path -------------------------------------
__device__ __forceinline__ int best_code(unsigned long long b) {
    return KD - 1 - (int)(uint32_t)(b & 0xFFFFFFFFull);
}

__global__ void k_count() {
    int idx = blockIdx.x * 256 + threadIdx.x;
    atomicAdd(&d_cnt[best_code(d_best[idx])], 1);
}

__global__ void k_scan() {   // 1 block, 1024 threads: exclusive scan
    __shared__ int s[1024];
    int t = threadIdx.x;
    int v = d_cnt[t];
    s[t] = v; __syncthreads();
    for (int o = 1; o < 1024; o <<= 1) {
        int add = (t >= o) ? s[t-o] : 0;
        __syncthreads();
        s[t] += add;
        __syncthreads();
    }
    d_off[t] = s[t] - v;
    d_cur[t] = s[t] - v;
}

__global__ void k_fill() {
    int idx = blockIdx.x * 256 + threadIdx.x;
    int code = best_code(d_best[idx]);
    int pos = atomicAdd(&d_cur[code], 1);
    d_rowlist[pos] = idx;
}

__global__ void k_update_codes(const float* __restrict__ uw) {
    __shared__ float red[256];
    int k = blockIdx.x, ch = threadIdx.x;
    int cnt = d_cnt[k], off = d_off[k];
    float sum = 0.f;
    for (int t = 0; t < cnt; t++) {
        int row = d_rowlist[off + t];
        sum += __half2float(d_xfh[(size_t)row*Cc + ch]);
    }
    float em = sum / ((float)cnt + EPS_Z);
    float mv = uw[(size_t)k*Cc + ch]*RATE + em*(1.0f - RATE);
    d_mnew[(size_t)k*Cc + ch] = mv;
    red[ch] = mv*mv; __syncthreads();
    for (int o = 128; o; o >>= 1) {
        if (ch < o) red[ch] += red[ch+o];
        __syncthreads();
    }
    float inv = 1.0f / fmaxf(sqrtf(red[0]), EPS_NORM);
    float mnv = mv*inv;
    float qp, qn;
    pow_pair(mnv, d_p[ch], qp, qn);
    d_kk[(size_t)k*(2*Cc) + ch]      = qp;
    d_kk[(size_t)k*(2*Cc) + Cc + ch] = qn;
}

__global__ void k_kmean() {  // grid (2, 8), 256 threads
    int col = blockIdx.x * 256 + threadIdx.x;
    int r0 = blockIdx.y * 128;
    float s = 0.f;
    for (int r = r0; r < r0 + 128; r++) s += d_kk[(size_t)r*(2*Cc) + col];
    atomicAdd(&d_kmean[col], s * (1.0f / KD));
}

// KV + fused transpose/XOR/fp16: BmatTh[j][rdest] = kvfull[r][j]
// kvfull[r][j] = sum_k kk[k][r] * mnew[k][j]; rdest = (j<128) ? r : r^256
__global__ __launch_bounds__(256)
void k_gemm_kv()
{
    __shared__ float As[16][68];
    __shared__ float Bs[16][68];
    int tid = threadIdx.x;
    int tx = tid & 15, ty = tid >> 4;
    int rowBase = blockIdx.y * 64, colBase = blockIdx.x * 64;
    float acc[4][4] = {};
    for (int k0 = 0; k0 < KD; k0 += 16) {
        #pragma unroll
        for (int e = 0; e < 4; e++) {
            int t = tid + e*256;
            int kk = t >> 6, r = t & 63;
            As[kk][r] = d_kk[(size_t)(k0 + kk)*(2*Cc) + rowBase + r];
        }
        #pragma unroll
        for (int e = 0; e < 4; e++) {
            int t = tid + e*256;
            int kk = t >> 6, c = t & 63;
            Bs[kk][c] = d_mnew[(size_t)(k0 + kk)*Cc + colBase + c];
        }
        __syncthreads();
        #pragma unroll
        for (int kk = 0; kk < 16; kk++) {
            float a[4], bv[4];
            #pragma unroll
            for (int i = 0; i < 4; i++) a[i]  = As[kk][ty*4 + i];
            #pragma unroll
            for (int j = 0; j < 4; j++) bv[j] = Bs[kk][tx*4 + j];
            #pragma unroll
            for (int i = 0; i < 4; i++)
                #pragma unroll
                for (int j = 0; j < 4; j++) acc[i][j] += a[i]*bv[j];
        }
        __syncthreads();
    }
    #pragma unroll
    for (int i = 0; i < 4; i++) {
        int r = rowBase + ty*4 + i;
        #pragma unroll
        for (int j = 0; j < 4; j++) {
            int jc = colBase + tx*4 + j;
            int rdest = (jc < Cc/2) ? r : (r ^ Cc);
            d_BmatTh[(size_t)jc*(2*Cc) + rdest] = __float2half(acc[i][j]);
        }
    }
}

// ---------------- z from fp16 qcat (one warp per row) -------------------------
__global__ void k_zrow() {
    int row  = blockIdx.x * 8 + (threadIdx.x >> 5);
    int lane = threadIdx.x & 31;
    const __half2* q = (const __half2*)(d_qcat + (size_t)row * (2*Cc));
    float s1 = 0.f, s2 = 0.f;
    #pragma unroll
    for (int t = 0; t < 8; t++) {
        int c2 = lane + t*32;           // half2 index 0..255
        float2 qf = __half22float2(q[c2]);
        int c = 2*c2;
        float k1a = d_kmean[c],       k1b = d_kmean[c+1];
        float k2a = d_kmean[c ^ Cc],  k2b = d_kmean[(c+1) ^ Cc];
        s1 += qf.x*k1a + qf.y*k1b;
        s2 += qf.x*k2a + qf.y*k2b;
    }
    #pragma unroll
    for (int o = 16; o; o >>= 1) {
        s1 += __shfl_xor_sync(0xffffffffu, s1, o);
        s2 += __shfl_xor_sync(0xffffffffu, s2, o);
    }
    if (lane == 0) {
        d_z [row] = 1.0f / (s1 + EPS_Z);
        d_z2[row] = 1.0f / (s2 + EPS_Z);
    }
}

// ---------------- fused depthwise conv + gate + transpose-out ----------------
__global__ void k_convout(const float* __restrict__ wgt, const float* __restrict__ bias,
                          float* __restrict__ out) {
    __shared__ float tile[32][33];
    int b  = blockIdx.z;
    int s0 = blockIdx.x * 32, c0 = blockIdx.y * 32;
    int tx = threadIdx.x, ty = threadIdx.y;
    int ch = c0 + tx;
    float w[9];
    #pragma unroll
    for (int k = 0; k < 9; k++) w[k] = wgt[ch*9 + k];
    float bs = bias[ch];
    #pragma unroll
    for (int pi = ty; pi < 32; pi += 8) {
        int s = s0 + pi;
        int h = s >> 6, wc = s & 63;
        size_t i = (size_t)b*HW + s;
        float center = d_xo[i*Cc + ch];
        float acc = bs;
        #pragma unroll
        for (int kh = 0; kh < 3; kh++) {
            int hh = h + kh - 1;
            if (hh < 0 || hh >= Hh) continue;
            #pragma unroll
            for (int kw = 0; kw < 3; kw++) {
                int ww2 = wc + kw - 1;
                if (ww2 < 0 || ww2 >= Ww) continue;
                acc += w[kh*3 + kw] * d_xo[(i + (kh-1)*Ww + (kw-1))*Cc + ch];
            }
        }
        tile[pi][tx] = (center + acc) * d_g[i*Cc + ch];
    }
    __syncthreads();
    #pragma unroll
    for (int r = ty; r < 32; r += 8)
        out[((size_t)(b*Cc + c0 + r))*HW + s0 + tx] = tile[tx][r];
}

// ---------------- launch -----------------------------------------------------
extern "C" void kernel_launch(void* const* d_in, const int* in_sizes, int n_in,
                              void* d_out, int out_size)
{
    const float* x       = (const float*)d_in[0];
    const float* units_w = (const float*)d_in[1];
    const float* power   = (const float*)d_in[2];
    const float* g_w     = (const float*)d_in[3];
    const float* g_b     = (const float*)d_in[4];
    const float* dwc_w   = (const float*)d_in[5];
    const float* dwc_b   = (const float*)d_in[6];

    float* out   = (float*)d_out;                  // (B,C,H,W)
    float* score = (float*)d_out + OUT_ELEMS;      // (N, K)

    void *p_xfh, *p_g, *p_xo, *p_qcat, *p_bigBh, *p_bmatTh;
    cudaGetSymbolAddress(&p_xfh,    d_xfh);
    cudaGetSymbolAddress(&p_g,      d_g);
    cudaGetSymbolAddress(&p_xo,     d_xo);
    cudaGetSymbolAddress(&p_qcat,   d_qcat);
    cudaGetSymbolAddress(&p_bigBh,  d_bigBh);
    cudaGetSymbolAddress(&p_bmatTh, d_BmatTh);

    static bool attrSet = false;
    if (!attrSet) {
        cudaFuncSetAttribute(k_mma<3>, cudaFuncAttributeMaxDynamicSharedMemorySize, MMA_SMEM_BYTES);
        cudaFuncSetAttribute(k_mma<2>, cudaFuncAttributeMaxDynamicSharedMemorySize, MMA_SMEM_BYTES);
        attrSet = true;
    }

    k_init<<<(Cc*Cc)/256, 256>>>(power, g_w);
    k_norm_units<<<KD, 256>>>(units_w);
    k_transnorm<<<dim3(HW/32, Bb), 256>>>(x);

    // merged: [g | score] = xfh @ bigB^T  (fp16 mma, fused bias / rinv+argmax)
    k_mma<3><<<dim3((Cc+KD)/128, Nn/128), 256, MMA_SMEM_BYTES>>>(
        (const __half*)p_xfh, (const __half*)p_bigBh, (float*)p_g, score, g_b, Cc, 1.f);

    k_count<<<Nn/256, 256>>>();
    k_scan<<<1, 1024>>>();
    k_fill<<<Nn/256, 256>>>();
    k_update_codes<<<KD, 256>>>(units_w);
    k_kmean<<<dim3(2, 8), 256>>>();
    k_gemm_kv<<<dim3(Cc/64, (2*Cc)/64), 256>>>();

    k_zrow<<<Nn/8, 256>>>();
    // xo = qcat @ BmatTh^T * z/N   (fp16 mma)
    k_mma<2><<<dim3(Cc/128, Nn/128), 256, MMA_SMEM_BYTES>>>(
        (const __half*)p_qcat, (const __half*)p_bmatTh, (float*)p_xo, nullptr, nullptr, 2*Cc, 1.0f/(float)Nn);

    dim3 tb(32, 8);
    k_convout<<<dim3(HW/32, Cc/32, Bb), tb>>>(dwc_w, dwc_b, out);
}